// round 15
// baseline (speedup 1.0000x reference)
#include <cuda_runtime.h>
#include <cuda_bf16.h>
#include <cuda_fp16.h>
#include <math.h>
#include <float.h>
#include <stdint.h>

// ---------------------------------------------------------------------------
// Problem constants
// ---------------------------------------------------------------------------
#define BATCH 2
#define SEQ   2048
#define EMB   2048
#define HEADS 16
#define DHEAD 128
#define MTOT  (BATCH*SEQ)     // 4096
#define NQKV  (3*EMB)         // 6144
#define BHT   (BATCH*HEADS)   // 32
#define KDIM  2048

// ---------------------------------------------------------------------------
// Global scratch
// ---------------------------------------------------------------------------
__device__ float2 g_rope[(size_t)SEQ * 64];

__device__ __nv_bfloat16 g_qhi[(size_t)BHT * SEQ * DHEAD];
__device__ __nv_bfloat16 g_qlo[(size_t)BHT * SEQ * DHEAD];
__device__ __nv_bfloat16 g_khi[(size_t)BHT * SEQ * DHEAD];
__device__ __nv_bfloat16 g_klo[(size_t)BHT * SEQ * DHEAD];
__device__ __nv_bfloat16 g_vhi[(size_t)BHT * SEQ * DHEAD];
__device__ __nv_bfloat16 g_vlo[(size_t)BHT * SEQ * DHEAD];

__device__ __half g_xh16[(size_t)MTOT * EMB];
__device__ __half g_xl16[(size_t)MTOT * EMB];
__device__ __half g_wq16[(size_t)NQKV * KDIM];

__device__ __nv_bfloat16 g_ahi[(size_t)MTOT * EMB];
__device__ __nv_bfloat16 g_alo[(size_t)MTOT * EMB];
__device__ __nv_bfloat16 g_wohi[(size_t)EMB * KDIM];
__device__ __nv_bfloat16 g_wolo[(size_t)EMB * KDIM];

// ---------------------------------------------------------------------------
// PTX helpers (sm_100 BASELINE only)
// ---------------------------------------------------------------------------
__device__ __forceinline__ uint32_t smem_u32(const void* p) {
    uint32_t a;
    asm("{ .reg .u64 t; cvta.to.shared.u64 t, %1; cvt.u32.u64 %0, t; }" : "=r"(a) : "l"(p));
    return a;
}
__device__ __forceinline__ void cp16(uint32_t s, const void* g) {
    asm volatile("cp.async.cg.shared.global [%0], [%1], 16;" :: "r"(s), "l"(g));
}
#define CP_COMMIT() asm volatile("cp.async.commit_group;" ::: "memory")
#define CP_WAIT(N)  asm volatile("cp.async.wait_group %0;" :: "n"(N) : "memory")

__device__ __forceinline__ void ldsm_x4(uint32_t r[4], uint32_t addr) {
    asm volatile("ldmatrix.sync.aligned.m8n8.x4.shared.b16 {%0,%1,%2,%3}, [%4];"
                 : "=r"(r[0]), "=r"(r[1]), "=r"(r[2]), "=r"(r[3]) : "r"(addr));
}
__device__ __forceinline__ void ldsm_x4_t(uint32_t r[4], uint32_t addr) {
    asm volatile("ldmatrix.sync.aligned.m8n8.x4.trans.shared.b16 {%0,%1,%2,%3}, [%4];"
                 : "=r"(r[0]), "=r"(r[1]), "=r"(r[2]), "=r"(r[3]) : "r"(addr));
}
__device__ __forceinline__ void mma_bf16(float c[4], const uint32_t a[4],
                                         uint32_t b0, uint32_t b1) {
    asm volatile("mma.sync.aligned.m16n8k16.row.col.f32.bf16.bf16.f32 "
                 "{%0,%1,%2,%3}, {%4,%5,%6,%7}, {%8,%9}, {%0,%1,%2,%3};"
                 : "+f"(c[0]), "+f"(c[1]), "+f"(c[2]), "+f"(c[3])
                 : "r"(a[0]), "r"(a[1]), "r"(a[2]), "r"(a[3]), "r"(b0), "r"(b1));
}
__device__ __forceinline__ void mma_fp16(float c[4], const uint32_t a[4],
                                         uint32_t b0, uint32_t b1) {
    asm volatile("mma.sync.aligned.m16n8k16.row.col.f32.f16.f16.f32 "
                 "{%0,%1,%2,%3}, {%4,%5,%6,%7}, {%8,%9}, {%0,%1,%2,%3};"
                 : "+f"(c[0]), "+f"(c[1]), "+f"(c[2]), "+f"(c[3])
                 : "r"(a[0]), "r"(a[1]), "r"(a[2]), "r"(a[3]), "r"(b0), "r"(b1));
}
__device__ __forceinline__ float ex2f(float x) {
    float y; asm("ex2.approx.ftz.f32 %0, %1;" : "=f"(y) : "f"(x)); return y;
}
__device__ __forceinline__ uint32_t pack_bf16x2(float a, float b) {
    __nv_bfloat162 t = __floats2bfloat162_rn(a, b);
    return *reinterpret_cast<uint32_t*>(&t);
}
__device__ __forceinline__ uint32_t pack_f16x2(float a, float b) {
    __half2 t = __floats2half2_rn(a, b);
    return *reinterpret_cast<uint32_t*>(&t);
}

// ===========================================================================
// QKV GEMM + fused RoPE epilogue. fp16 2-pass, pass-major order.
// Tile 64x128 (BM=64 -> 3072 CTAs, 10.4 waves @2 CTA/SM: tail idle ~6%).
// Warp tile 32x32 (2m x 4n warps). BK=32, 3 stages (48KB).
// ===========================================================================
#define GBKF   32
#define NCHF   (KDIM / GBKF)
#define MATF_A 4096                  // 64 x 32 fp16
#define MATF_B 8192                  // 128 x 32 fp16
#define STAGEF (2*MATF_A + MATF_B)   // 16384
#define GEMMF_SMEM (3 * STAGEF)      // 49152; epi tile 64*132*4=33792 fits

__device__ __forceinline__ void load_stage_f(uint32_t st,
    const __half* __restrict__ Ah, const __half* __restrict__ Al,
    const __half* __restrict__ Bh, int k0, int tid)
{
    {   // A halves: 256 16B units each
        int r = tid >> 2, u = tid & 3;
        size_t   goff = (size_t)r * KDIM + k0 + u * 8;
        uint32_t soff = r * 64 + ((u ^ ((r >> 1) & 3)) << 4);
        cp16(st + soff,          Ah + goff);
        cp16(st + MATF_A + soff, Al + goff);
    }
#pragma unroll
    for (int i = 0; i < 2; i++) {    // B: 512 16B units
        int uid = tid + (i << 8);
        int r = uid >> 2, u = uid & 3;
        size_t   goff = (size_t)r * KDIM + k0 + u * 8;
        uint32_t soff = r * 64 + ((u ^ ((r >> 1) & 3)) << 4);
        cp16(st + 2 * MATF_A + soff, Bh + goff);
    }
}

__device__ __forceinline__ void compute_chunk_f(uint32_t st, int lane, int wm, int wn,
                                                float acc[2][4][4])
{
    const int aRow0 = wm * 32 + ((lane >> 3) & 1) * 8 + (lane & 7);
    const int bRow0 = wn * 32 + ((lane >> 4) << 3) + (lane & 7);
    const int au = (lane >> 4);
    const int bu = ((lane >> 3) & 1);
#pragma unroll
    for (int ks = 0; ks < 2; ks++) {
        uint32_t ah[2][4], al[2][4];
#pragma unroll
        for (int mt = 0; mt < 2; mt++) {
            int row = aRow0 + mt * 16;
            int u   = ks * 2 + au;
            uint32_t off = row * 64 + ((u ^ ((row >> 1) & 3)) << 4);
            ldsm_x4(ah[mt], st + off);
            ldsm_x4(al[mt], st + MATF_A + off);
        }
        uint32_t bh[2][4];
#pragma unroll
        for (int ng = 0; ng < 2; ng++) {
            int row = bRow0 + ng * 16;
            int u   = ks * 2 + bu;
            uint32_t off = row * 64 + ((u ^ ((row >> 1) & 3)) << 4);
            ldsm_x4(bh[ng], st + 2 * MATF_A + off);
        }
        // pass 1: A-hi (8 distinct accumulators)
#pragma unroll
        for (int mt = 0; mt < 2; mt++)
#pragma unroll
            for (int ng = 0; ng < 2; ng++) {
                mma_fp16(acc[mt][ng * 2],     ah[mt], bh[ng][0], bh[ng][1]);
                mma_fp16(acc[mt][ng * 2 + 1], ah[mt], bh[ng][2], bh[ng][3]);
            }
        // pass 2: A-lo
#pragma unroll
        for (int mt = 0; mt < 2; mt++)
#pragma unroll
            for (int ng = 0; ng < 2; ng++) {
                mma_fp16(acc[mt][ng * 2],     al[mt], bh[ng][0], bh[ng][1]);
                mma_fp16(acc[mt][ng * 2 + 1], al[mt], bh[ng][2], bh[ng][3]);
            }
    }
}

__global__ __launch_bounds__(256, 2)
void gemm_qkv_rope_kernel(const __half* __restrict__ Ahi, const __half* __restrict__ Alo,
                          const __half* __restrict__ Bhi, const float* __restrict__ bias,
                          __nv_bfloat16* __restrict__ Qh, __nv_bfloat16* __restrict__ Ql,
                          __nv_bfloat16* __restrict__ Kh, __nv_bfloat16* __restrict__ Kl,
                          __nv_bfloat16* __restrict__ Vh, __nv_bfloat16* __restrict__ Vl)
{
    extern __shared__ __align__(1024) char sm[];
    const uint32_t sbase = smem_u32(sm);
    const int tid  = threadIdx.x;
    const int lane = tid & 31;
    const int wid  = tid >> 5;
    const int wm   = wid >> 2;       // 2 along M (32 rows each)
    const int wn   = wid & 3;        // 4 along N (32 cols each)
    const int m0 = blockIdx.y * 64;
    const int n0 = blockIdx.x * 128;

    const __half* Ahb = Ahi + (size_t)m0 * KDIM;
    const __half* Alb = Alo + (size_t)m0 * KDIM;
    const __half* Bhb = Bhi + (size_t)n0 * KDIM;

    float acc[2][4][4];
#pragma unroll
    for (int a = 0; a < 2; a++)
#pragma unroll
        for (int b = 0; b < 4; b++)
#pragma unroll
            for (int c = 0; c < 4; c++) acc[a][b][c] = 0.f;

    load_stage_f(sbase,          Ahb, Alb, Bhb, 0, tid);
    CP_COMMIT();
    load_stage_f(sbase + STAGEF, Ahb, Alb, Bhb, GBKF, tid);
    CP_COMMIT();

    uint32_t stage_off[3] = {0, STAGEF, 2 * STAGEF};
    for (int c = 0; c < NCHF; c++) {
        CP_WAIT(1);
        __syncthreads();
        compute_chunk_f(sbase + stage_off[c % 3], lane, wm, wn, acc);
        if (c + 2 < NCHF)
            load_stage_f(sbase + stage_off[(c + 2) % 3],
                         Ahb, Alb, Bhb, (c + 2) * GBKF, tid);
        CP_COMMIT();
    }

    // ---- fused RoPE epilogue ----
    float* eps = (float*)sm;                 // [64][132] fp32
    __syncthreads();

    const int g   = lane >> 2;
    const int tg2 = (lane & 3) * 2;
#pragma unroll
    for (int mt = 0; mt < 2; mt++) {
        int r0 = wm * 32 + mt * 16 + g;
#pragma unroll
        for (int ng = 0; ng < 4; ng++) {
            int col = wn * 32 + ng * 8 + tg2;
            *(float2*)&eps[r0 * 132 + col]       = make_float2(acc[mt][ng][0], acc[mt][ng][1]);
            *(float2*)&eps[(r0 + 8) * 132 + col] = make_float2(acc[mt][ng][2], acc[mt][ng][3]);
        }
    }
    __syncthreads();

    const int mat = n0 >> 11;                // 0=Q, 1=K, 2=V
    const int h   = (n0 & 2047) >> 7;        // head within matrix
    __nv_bfloat16* Hi1; __nv_bfloat16* Lo1;
    if (mat == 0)      { Hi1 = Qh; Lo1 = Ql; }
    else if (mat == 1) { Hi1 = Kh; Lo1 = Kl; }
    else               { Hi1 = Vh; Lo1 = Vl; }

#pragma unroll 4
    for (int p = 0; p < 16; p++) {
        int pid = tid + (p << 8);            // 0..4095
        int r = pid >> 6;                    // tile row 0..63
        int j = pid & 63;                    // rope pair index
        int t = m0 + r;
        int n = t & (SEQ - 1);
        int b = t >> 11;

        float v1 = eps[r * 132 + j]      + bias[n0 + j];
        float v2 = eps[r * 132 + j + 64] + bias[n0 + j + 64];
        float o1, o2;
        if (mat < 2) {
            float2 cssn = g_rope[(n << 6) + j];
            o1 = v1 * cssn.x - v2 * cssn.y;
            o2 = v1 * cssn.y + v2 * cssn.x;
        } else {
            o1 = v1; o2 = v2;
        }
        size_t o = ((size_t)(b * HEADS + h) * SEQ + n) * DHEAD + j;
        float h1 = __bfloat162float(__float2bfloat16(o1));
        float h2 = __bfloat162float(__float2bfloat16(o2));
        Hi1[o]      = __float2bfloat16(o1);
        Lo1[o]      = __float2bfloat16(o1 - h1);
        Hi1[o + 64] = __float2bfloat16(o2);
        Lo1[o + 64] = __float2bfloat16(o2 - h2);
    }
}

// ===========================================================================
// Out-proj GEMM: bf16 3-pass, pass-major order (unchanged from R13).
// ===========================================================================
#define GBK2   32
#define NCH2   (KDIM / GBK2)
#define MATB2  8192
#define STAGE2 (4 * MATB2)
#define GEMM_SMEM (3 * STAGE2)

__device__ __forceinline__ void load_stage2(uint32_t st,
    const __nv_bfloat16* __restrict__ Ah, const __nv_bfloat16* __restrict__ Al,
    const __nv_bfloat16* __restrict__ Bh, const __nv_bfloat16* __restrict__ Bl,
    int k0, int tid)
{
#pragma unroll
    for (int i = 0; i < 2; i++) {
        int uid = tid + (i << 8);
        int r = uid >> 2, u = uid & 3;
        size_t   goff = (size_t)r * KDIM + k0 + u * 8;
        uint32_t soff = r * 64 + ((u ^ ((r >> 1) & 3)) << 4);
        cp16(st + soff,             Ah + goff);
        cp16(st + MATB2 + soff,     Al + goff);
        cp16(st + 2 * MATB2 + soff, Bh + goff);
        cp16(st + 3 * MATB2 + soff, Bl + goff);
    }
}

__device__ __forceinline__ void compute_chunk2(uint32_t st, int lane, int wm, int wn,
                                               float acc[2][8][4])
{
    const int aRow0 = wm * 32 + ((lane >> 3) & 1) * 8 + (lane & 7);
    const int bRow0 = wn * 64 + ((lane >> 4) << 3) + (lane & 7);
    const int au = (lane >> 4);
    const int bu = ((lane >> 3) & 1);
#pragma unroll
    for (int ks = 0; ks < 2; ks++) {
        uint32_t ah[2][4], al[2][4];
#pragma unroll
        for (int mt = 0; mt < 2; mt++) {
            int row = aRow0 + mt * 16;
            int u   = ks * 2 + au;
            uint32_t off = row * 64 + ((u ^ ((row >> 1) & 3)) << 4);
            ldsm_x4(ah[mt], st + off);
            ldsm_x4(al[mt], st + MATB2 + off);
        }
        uint32_t bh[4][4], bl[4][4];
#pragma unroll
        for (int ng = 0; ng < 4; ng++) {
            int row = bRow0 + ng * 16;
            int u   = ks * 2 + bu;
            uint32_t off = row * 64 + ((u ^ ((row >> 1) & 3)) << 4);
            ldsm_x4(bh[ng], st + 2 * MATB2 + off);
            ldsm_x4(bl[ng], st + 3 * MATB2 + off);
        }
#pragma unroll
        for (int mt = 0; mt < 2; mt++)
#pragma unroll
            for (int ng = 0; ng < 4; ng++) {
                mma_bf16(acc[mt][ng * 2],     ah[mt], bh[ng][0], bh[ng][1]);
                mma_bf16(acc[mt][ng * 2 + 1], ah[mt], bh[ng][2], bh[ng][3]);
            }
#pragma unroll
        for (int mt = 0; mt < 2; mt++)
#pragma unroll
            for (int ng = 0; ng < 4; ng++) {
                mma_bf16(acc[mt][ng * 2],     al[mt], bh[ng][0], bh[ng][1]);
                mma_bf16(acc[mt][ng * 2 + 1], al[mt], bh[ng][2], bh[ng][3]);
            }
#pragma unroll
        for (int mt = 0; mt < 2; mt++)
#pragma unroll
            for (int ng = 0; ng < 4; ng++) {
                mma_bf16(acc[mt][ng * 2],     ah[mt], bl[ng][0], bl[ng][1]);
                mma_bf16(acc[mt][ng * 2 + 1], ah[mt], bl[ng][2], bl[ng][3]);
            }
    }
}

__global__ __launch_bounds__(256, 2)
void gemm_mma_kernel(const __nv_bfloat16* __restrict__ Ahi, const __nv_bfloat16* __restrict__ Alo,
                     const __nv_bfloat16* __restrict__ Bhi, const __nv_bfloat16* __restrict__ Blo,
                     const float* __restrict__ bias, float* __restrict__ C, int Nt)
{
    extern __shared__ __align__(1024) char sm[];
    const uint32_t sbase = smem_u32(sm);
    const int tid  = threadIdx.x;
    const int lane = tid & 31;
    const int wid  = tid >> 5;
    const int wm   = wid & 3;
    const int wn   = wid >> 2;
    const int m0 = blockIdx.y * 128;
    const int n0 = blockIdx.x * 128;

    const __nv_bfloat16* Ahb = Ahi + (size_t)m0 * KDIM;
    const __nv_bfloat16* Alb = Alo + (size_t)m0 * KDIM;
    const __nv_bfloat16* Bhb = Bhi + (size_t)n0 * KDIM;
    const __nv_bfloat16* Blb = Blo + (size_t)n0 * KDIM;

    float acc[2][8][4];
#pragma unroll
    for (int a = 0; a < 2; a++)
#pragma unroll
        for (int b = 0; b < 8; b++)
#pragma unroll
            for (int c = 0; c < 4; c++) acc[a][b][c] = 0.f;

    load_stage2(sbase,          Ahb, Alb, Bhb, Blb, 0, tid);
    CP_COMMIT();
    load_stage2(sbase + STAGE2, Ahb, Alb, Bhb, Blb, GBK2, tid);
    CP_COMMIT();

    uint32_t stage_off[3] = {0, STAGE2, 2 * STAGE2};
    for (int c = 0; c < NCH2; c++) {
        CP_WAIT(1);
        __syncthreads();
        compute_chunk2(sbase + stage_off[c % 3], lane, wm, wn, acc);
        if (c + 2 < NCH2)
            load_stage2(sbase + stage_off[(c + 2) % 3],
                        Ahb, Alb, Bhb, Blb, (c + 2) * GBK2, tid);
        CP_COMMIT();
    }

    const int g   = lane >> 2;
    const int tg2 = (lane & 3) * 2;
#pragma unroll
    for (int mt = 0; mt < 2; mt++) {
        int r0 = m0 + wm * 32 + mt * 16 + g;
#pragma unroll
        for (int ng = 0; ng < 8; ng++) {
            int col = n0 + wn * 64 + ng * 8 + tg2;
            float b0 = bias[col], b1 = bias[col + 1];
            float2 v0 = make_float2(acc[mt][ng][0] + b0, acc[mt][ng][1] + b1);
            float2 v1 = make_float2(acc[mt][ng][2] + b0, acc[mt][ng][3] + b1);
            *(float2*)&C[(size_t)r0 * Nt + col]       = v0;
            *(float2*)&C[(size_t)(r0 + 8) * Nt + col] = v1;
        }
    }
}

// ---------------------------------------------------------------------------
// Merged prep: Wqkv trans->fp16 | Wo trans->bf16 hi/lo | rope table | x split
// ---------------------------------------------------------------------------
#define WQ_BLKS ((NQKV/32)*(KDIM/32))     // 12288
#define WO_BLKS ((EMB/32)*(KDIM/32))      // 4096
#define RT_BLKS 512
#define XC_BLKS (MTOT*EMB/4/256)          // 8192
#define PREP_BLKS (WQ_BLKS + WO_BLKS + RT_BLKS + XC_BLKS)

__global__ __launch_bounds__(256)
void prep_all_kernel(const float* __restrict__ Wqkv, __half* __restrict__ Wq16,
                     const float* __restrict__ Wo,
                     __nv_bfloat16* __restrict__ Wohi, __nv_bfloat16* __restrict__ Wolo,
                     const float* __restrict__ X,
                     __half* __restrict__ Xhi, __half* __restrict__ Xlo)
{
    __shared__ float t[32][33];
    const int tid = threadIdx.x;
    const int bx = blockIdx.x;

    if (bx < WQ_BLKS) {
        const int n0 = (bx % (NQKV / 32)) * 32, k0 = (bx / (NQKV / 32)) * 32;
        {
            int row = tid >> 3, c4 = (tid & 7) * 4;
            float4 v = *(const float4*)&Wqkv[(size_t)(k0 + row) * NQKV + n0 + c4];
            t[row][c4] = v.x; t[row][c4 + 1] = v.y; t[row][c4 + 2] = v.z; t[row][c4 + 3] = v.w;
        }
        __syncthreads();
        {
            int n = tid >> 3, kc = (tid & 7) * 4;
            float f0 = t[kc][n], f1 = t[kc + 1][n], f2 = t[kc + 2][n], f3 = t[kc + 3][n];
            size_t o = (size_t)(n0 + n) * KDIM + k0 + kc;
            *(uint2*)&Wq16[o] = make_uint2(pack_f16x2(f0, f1), pack_f16x2(f2, f3));
        }
    } else if (bx < WQ_BLKS + WO_BLKS) {
        const int i = bx - WQ_BLKS;
        const int n0 = (i % (EMB / 32)) * 32, k0 = (i / (EMB / 32)) * 32;
        {
            int row = tid >> 3, c4 = (tid & 7) * 4;
            float4 v = *(const float4*)&Wo[(size_t)(k0 + row) * EMB + n0 + c4];
            t[row][c4] = v.x; t[row][c4 + 1] = v.y; t[row][c4 + 2] = v.z; t[row][c4 + 3] = v.w;
        }
        __syncthreads();
        {
            int n = tid >> 3, kc = (tid & 7) * 4;
            float f0 = t[kc][n], f1 = t[kc + 1][n], f2 = t[kc + 2][n], f3 = t[kc + 3][n];
#define HI(x) __bfloat162float(__float2bfloat16(x))
            uint32_t hp0 = pack_bf16x2(f0, f1), hp1 = pack_bf16x2(f2, f3);
            uint32_t lp0 = pack_bf16x2(f0 - HI(f0), f1 - HI(f1));
            uint32_t lp1 = pack_bf16x2(f2 - HI(f2), f3 - HI(f3));
#undef HI
            size_t o = (size_t)(n0 + n) * KDIM + k0 + kc;
            *(uint2*)&Wohi[o] = make_uint2(hp0, hp1);
            *(uint2*)&Wolo[o] = make_uint2(lp0, lp1);
        }
    } else if (bx < WQ_BLKS + WO_BLKS + RT_BLKS) {
        int idx = (bx - WQ_BLKS - WO_BLKS) * 256 + tid;
        if (idx >= SEQ * 64) return;
        int n = idx >> 6, j = idx & 63;
        float pf = __bfloat162float(__float2bfloat16(
                       (float)pow(10000.0, (double)j * (1.0 / 64.0))));
        float th = __bfloat162float(__float2bfloat16(1.0f / pf));
        float sn, cs;
        sincosf((float)n * th, &sn, &cs);
        g_rope[idx] = make_float2(cs, sn);
    } else {
        int i = (bx - WQ_BLKS - WO_BLKS - RT_BLKS) * 256 + tid;
        if (i >= MTOT * EMB / 4) return;
        float4 v = ((const float4*)X)[i];
        float f[4] = {v.x, v.y, v.z, v.w};
        float h[4];
#pragma unroll
        for (int j = 0; j < 4; j++) h[j] = __half2float(__float2half_rn(f[j]));
        ((uint2*)Xhi)[i] = make_uint2(pack_f16x2(f[0], f[1]), pack_f16x2(f[2], f[3]));
        ((uint2*)Xlo)[i] = make_uint2(pack_f16x2(f[0] - h[0], f[1] - h[1]),
                                      pack_f16x2(f[2] - h[2], f[3] - h[3]));
    }
}

// ---------------------------------------------------------------------------
// Flash attention (unchanged from R13)
// ---------------------------------------------------------------------------
#define FA_QBYTES   32768
#define FA_KVMAT    16384
#define FA_STAGE    (4 * FA_KVMAT)
#define FA_SMEM     (2 * FA_QBYTES + 2 * FA_STAGE)

__device__ __forceinline__ void fa_load_kv(uint32_t st,
    const __nv_bfloat16* kh, const __nv_bfloat16* kl,
    const __nv_bfloat16* vh, const __nv_bfloat16* vl, int tid)
{
#pragma unroll
    for (int i = 0; i < 4; i++) {
        int uid = tid + (i << 8);
        int r = uid >> 4, u = uid & 15;
        uint32_t so = r * 256 + ((u ^ (r & 7)) << 4);
        size_t go = (size_t)r * 128 + u * 8;
        cp16(st + so,                kh + go);
        cp16(st + FA_KVMAT + so,     kl + go);
        cp16(st + 2 * FA_KVMAT + so, vh + go);
        cp16(st + 3 * FA_KVMAT + so, vl + go);
    }
}

__global__ __launch_bounds__(256)
void flash_mma_kernel(const __nv_bfloat16* __restrict__ Qh, const __nv_bfloat16* __restrict__ Ql,
                      const __nv_bfloat16* __restrict__ Kh, const __nv_bfloat16* __restrict__ Kl,
                      const __nv_bfloat16* __restrict__ Vh, const __nv_bfloat16* __restrict__ Vl,
                      __nv_bfloat16* __restrict__ Ohi, __nv_bfloat16* __restrict__ Olo)
{
    extern __shared__ __align__(1024) char sm[];
    const uint32_t sb = smem_u32(sm);
    const int tid = threadIdx.x, lane = tid & 31, w = tid >> 5;
    const int qb = gridDim.x - 1 - blockIdx.x;
    const int bh = blockIdx.y;
    const int row_lo = qb * 128 + w * 16;
    const uint32_t sQh = sb, sQl = sb + FA_QBYTES;
    const uint32_t sKV = sb + 2 * FA_QBYTES;

    {
        const __nv_bfloat16* qhg = Qh + ((size_t)bh * SEQ + qb * 128) * DHEAD;
        const __nv_bfloat16* qlg = Ql + ((size_t)bh * SEQ + qb * 128) * DHEAD;
#pragma unroll
        for (int i = 0; i < 8; i++) {
            int uid = tid + (i << 8);
            int r = uid >> 4, u = uid & 15;
            uint32_t so = r * 256 + ((u ^ (r & 7)) << 4);
            size_t go = (size_t)r * 128 + u * 8;
            cp16(sQh + so, qhg + go);
            cp16(sQl + so, qlg + go);
        }
    }
    const __nv_bfloat16* khb = Kh + (size_t)bh * SEQ * DHEAD;
    const __nv_bfloat16* klb = Kl + (size_t)bh * SEQ * DHEAD;
    const __nv_bfloat16* vhb = Vh + (size_t)bh * SEQ * DHEAD;
    const __nv_bfloat16* vlb = Vl + (size_t)bh * SEQ * DHEAD;

    fa_load_kv(sKV, khb, klb, vhb, vlb, tid);
    CP_COMMIT();

    float O[16][4];
#pragma unroll
    for (int i = 0; i < 16; i++)
#pragma unroll
        for (int j = 0; j < 4; j++) O[i][j] = 0.f;
    float mrow0 = -1e30f, mrow1 = -1e30f, lrow0 = 0.f, lrow1 = 0.f;

    const float SC = 0.08838834764831845f * 1.4426950408889634f;
    const int nkb = 2 * qb + 2;

    for (int kb = 0; kb < nkb; kb++) {
        const uint32_t st = sKV + (kb & 1) * FA_STAGE;
        if (kb + 1 < nkb) {
            fa_load_kv(sKV + ((kb + 1) & 1) * FA_STAGE,
                       khb + (size_t)(kb + 1) * 64 * DHEAD, klb + (size_t)(kb + 1) * 64 * DHEAD,
                       vhb + (size_t)(kb + 1) * 64 * DHEAD, vlb + (size_t)(kb + 1) * 64 * DHEAD, tid);
            CP_COMMIT();
            CP_WAIT(1);
        } else {
            CP_WAIT(0);
        }
        __syncthreads();

        const bool skip = (kb * 64 > row_lo + 15);
        if (!skip) {
            float S[8][4];
#pragma unroll
            for (int i = 0; i < 8; i++)
#pragma unroll
                for (int j = 0; j < 4; j++) S[i][j] = 0.f;

            const int ar = w * 16 + (lane & 7) + ((lane >> 3) & 1) * 8;
            const int br_ = ((lane >> 4) << 3) + (lane & 7);
            const int au = (lane >> 4);
            const int bu = ((lane >> 3) & 1);
#pragma unroll
            for (int ks = 0; ks < 8; ks++) {
                uint32_t qa[4], ql4[4];
                uint32_t aoff = ar * 256 + (((2 * ks + au) ^ (ar & 7)) << 4);
                ldsm_x4(qa, sQh + aoff);
                ldsm_x4(ql4, sQl + aoff);
                uint32_t kh4[4][4], kl4[4][4];
#pragma unroll
                for (int ng = 0; ng < 4; ng++) {
                    int br = ng * 16 + br_;
                    uint32_t boff = br * 256 + (((2 * ks + bu) ^ (br & 7)) << 4);
                    ldsm_x4(kh4[ng], st + boff);
                    ldsm_x4(kl4[ng], st + FA_KVMAT + boff);
                }
#pragma unroll
                for (int ng = 0; ng < 4; ng++) {
                    mma_bf16(S[2 * ng],     qa, kh4[ng][0], kh4[ng][1]);
                    mma_bf16(S[2 * ng + 1], qa, kh4[ng][2], kh4[ng][3]);
                }
#pragma unroll
                for (int ng = 0; ng < 4; ng++) {
                    mma_bf16(S[2 * ng],     ql4, kh4[ng][0], kh4[ng][1]);
                    mma_bf16(S[2 * ng + 1], ql4, kh4[ng][2], kh4[ng][3]);
                }
#pragma unroll
                for (int ng = 0; ng < 4; ng++) {
                    mma_bf16(S[2 * ng],     qa, kl4[ng][0], kl4[ng][1]);
                    mma_bf16(S[2 * ng + 1], qa, kl4[ng][2], kl4[ng][3]);
                }
            }

            const int r0 = row_lo + (lane >> 2), r1 = r0 + 8;
            const int c00 = kb * 64 + (lane & 3) * 2;
            float m0p = -1e30f, m1p = -1e30f;
#pragma unroll
            for (int nt = 0; nt < 8; nt++) {
                int c = c00 + nt * 8;
#pragma unroll
                for (int j = 0; j < 4; j++) {
                    int col = c + (j & 1);
                    int row = (j < 2) ? r0 : r1;
                    float s = S[nt][j] * SC;
                    if (col > row) s = -1e30f;
                    S[nt][j] = s;
                }
                m0p = fmaxf(m0p, fmaxf(S[nt][0], S[nt][1]));
                m1p = fmaxf(m1p, fmaxf(S[nt][2], S[nt][3]));
            }
            m0p = fmaxf(m0p, __shfl_xor_sync(0xffffffffu, m0p, 1));
            m0p = fmaxf(m0p, __shfl_xor_sync(0xffffffffu, m0p, 2));
            m1p = fmaxf(m1p, __shfl_xor_sync(0xffffffffu, m1p, 1));
            m1p = fmaxf(m1p, __shfl_xor_sync(0xffffffffu, m1p, 2));
            const float mn0 = fmaxf(mrow0, m0p), mn1 = fmaxf(mrow1, m1p);
            const float a0 = ex2f(mrow0 - mn0), a1 = ex2f(mrow1 - mn1);
            mrow0 = mn0; mrow1 = mn1;
            float ps0 = 0.f, ps1 = 0.f;
#pragma unroll
            for (int nt = 0; nt < 8; nt++) {
                S[nt][0] = ex2f(S[nt][0] - mn0);
                S[nt][1] = ex2f(S[nt][1] - mn0);
                S[nt][2] = ex2f(S[nt][2] - mn1);
                S[nt][3] = ex2f(S[nt][3] - mn1);
                ps0 += S[nt][0] + S[nt][1];
                ps1 += S[nt][2] + S[nt][3];
            }
            lrow0 = lrow0 * a0 + ps0;
            lrow1 = lrow1 * a1 + ps1;
#pragma unroll
            for (int dt = 0; dt < 16; dt++) {
                O[dt][0] *= a0; O[dt][1] *= a0;
                O[dt][2] *= a1; O[dt][3] *= a1;
            }

            const int vr_ = (lane & 7) + ((lane >> 3) & 1) * 8;
            const int vu_ = (lane >> 4);
#pragma unroll
            for (int ks2 = 0; ks2 < 4; ks2++) {
                uint32_t ph[4], pl[4];
                {
                    float p0 = S[2 * ks2][0], p1 = S[2 * ks2][1];
                    float p2 = S[2 * ks2][2], p3 = S[2 * ks2][3];
                    float p4 = S[2 * ks2 + 1][0], p5 = S[2 * ks2 + 1][1];
                    float p6 = S[2 * ks2 + 1][2], p7 = S[2 * ks2 + 1][3];
                    ph[0] = pack_bf16x2(p0, p1);
                    ph[1] = pack_bf16x2(p2, p3);
                    ph[2] = pack_bf16x2(p4, p5);
                    ph[3] = pack_bf16x2(p6, p7);
#define RES(x) ((x) - __bfloat162float(__float2bfloat16(x)))
                    pl[0] = pack_bf16x2(RES(p0), RES(p1));
                    pl[1] = pack_bf16x2(RES(p2), RES(p3));
                    pl[2] = pack_bf16x2(RES(p4), RES(p5));
                    pl[3] = pack_bf16x2(RES(p6), RES(p7));
#undef RES
                }
                int vr = ks2 * 16 + vr_;
#pragma unroll
                for (int dp = 0; dp < 8; dp++) {
                    uint32_t voff = vr * 256 + (((dp * 2 + vu_) ^ (vr & 7)) << 4);
                    uint32_t vh4[4], vl4[4];
                    ldsm_x4_t(vh4, st + 2 * FA_KVMAT + voff);
                    ldsm_x4_t(vl4, st + 3 * FA_KVMAT + voff);
                    mma_bf16(O[2 * dp],     ph, vh4[0], vh4[1]);
                    mma_bf16(O[2 * dp + 1], ph, vh4[2], vh4[3]);
                    mma_bf16(O[2 * dp],     pl, vh4[0], vh4[1]);
                    mma_bf16(O[2 * dp + 1], pl, vh4[2], vh4[3]);
                    mma_bf16(O[2 * dp],     ph, vl4[0], vl4[1]);
                    mma_bf16(O[2 * dp + 1], ph, vl4[2], vl4[3]);
                }
            }
        }
        __syncthreads();
    }

    float l0 = lrow0;
    l0 += __shfl_xor_sync(0xffffffffu, l0, 1);
    l0 += __shfl_xor_sync(0xffffffffu, l0, 2);
    float l1 = lrow1;
    l1 += __shfl_xor_sync(0xffffffffu, l1, 1);
    l1 += __shfl_xor_sync(0xffffffffu, l1, 2);
    const float inv0 = 1.0f / l0, inv1 = 1.0f / l1;

    const int b = bh >> 4, h = bh & 15;
    const int n0r = row_lo + (lane >> 2);
    size_t base0 = ((size_t)(b * SEQ + n0r)) * EMB + h * DHEAD + (lane & 3) * 2;
    size_t base1 = base0 + (size_t)8 * EMB;
#pragma unroll
    for (int dt = 0; dt < 16; dt++) {
        float x0 = O[dt][0] * inv0, x1 = O[dt][1] * inv0;
        float x2 = O[dt][2] * inv1, x3 = O[dt][3] * inv1;
        float h0 = __bfloat162float(__float2bfloat16(x0));
        float h1 = __bfloat162float(__float2bfloat16(x1));
        float h2 = __bfloat162float(__float2bfloat16(x2));
        float h3 = __bfloat162float(__float2bfloat16(x3));
        *(uint32_t*)&Ohi[base0 + dt * 8] = pack_bf16x2(x0, x1);
        *(uint32_t*)&Olo[base0 + dt * 8] = pack_bf16x2(x0 - h0, x1 - h1);
        *(uint32_t*)&Ohi[base1 + dt * 8] = pack_bf16x2(x2, x3);
        *(uint32_t*)&Olo[base1 + dt * 8] = pack_bf16x2(x2 - h2, x3 - h3);
    }
}

// ---------------------------------------------------------------------------
// Launch
// ---------------------------------------------------------------------------
extern "C" void kernel_launch(void* const* d_in, const int* in_sizes, int n_in,
                              void* d_out, int out_size)
{
    const float* x    = (const float*)d_in[0];
    const float* Wqkv = (const float*)d_in[1];
    const float* bqkv = (const float*)d_in[2];
    const float* Wo   = (const float*)d_in[3];
    const float* bo   = (const float*)d_in[4];
    float* out = (float*)d_out;
    (void)in_sizes; (void)n_in; (void)out_size;

    __nv_bfloat16 *qhi, *qlo, *khi, *klo, *vhi, *vlo, *ahi, *alo, *wohi, *wolo;
    __half *xh16, *xl16, *wq16;
    cudaGetSymbolAddress((void**)&qhi,  g_qhi);
    cudaGetSymbolAddress((void**)&qlo,  g_qlo);
    cudaGetSymbolAddress((void**)&khi,  g_khi);
    cudaGetSymbolAddress((void**)&klo,  g_klo);
    cudaGetSymbolAddress((void**)&vhi,  g_vhi);
    cudaGetSymbolAddress((void**)&vlo,  g_vlo);
    cudaGetSymbolAddress((void**)&ahi,  g_ahi);
    cudaGetSymbolAddress((void**)&alo,  g_alo);
    cudaGetSymbolAddress((void**)&wohi, g_wohi);
    cudaGetSymbolAddress((void**)&wolo, g_wolo);
    cudaGetSymbolAddress((void**)&xh16, g_xh16);
    cudaGetSymbolAddress((void**)&xl16, g_xl16);
    cudaGetSymbolAddress((void**)&wq16, g_wq16);

    cudaFuncSetAttribute(gemm_qkv_rope_kernel,
                         cudaFuncAttributeMaxDynamicSharedMemorySize, GEMMF_SMEM);
    cudaFuncSetAttribute(gemm_mma_kernel,
                         cudaFuncAttributeMaxDynamicSharedMemorySize, GEMM_SMEM);
    cudaFuncSetAttribute(flash_mma_kernel,
                         cudaFuncAttributeMaxDynamicSharedMemorySize, FA_SMEM);

    // 1) merged prep (one launch)
    prep_all_kernel<<<PREP_BLKS, 256>>>(Wqkv, wq16, Wo, wohi, wolo, x, xh16, xl16);

    // 2) QKV projection + fused RoPE/split (BM=64: 3072 CTAs, low tail)
    gemm_qkv_rope_kernel<<<dim3(NQKV / 128, MTOT / 64), 256, GEMMF_SMEM>>>(
        xh16, xl16, wq16, bqkv, qhi, qlo, khi, klo, vhi, vlo);

    // 3) Flash attention -> out-proj A hi/lo directly
    flash_mma_kernel<<<dim3(SEQ / 128, BHT), 256, FA_SMEM>>>(
        qhi, qlo, khi, klo, vhi, vlo, ahi, alo);

    // 4) Output projection — bf16 3-pass
    gemm_mma_kernel<<<dim3(EMB / 128, MTOT / 128), 256, GEMM_SMEM>>>(
        ahi, alo, wohi, wolo, bo, out, EMB);
}

// round 16
// speedup vs baseline: 1.0804x; 1.0804x over previous
#include <cuda_runtime.h>
#include <cuda_bf16.h>
#include <cuda_fp16.h>
#include <math.h>
#include <float.h>
#include <stdint.h>

// ---------------------------------------------------------------------------
// Problem constants
// ---------------------------------------------------------------------------
#define BATCH 2
#define SEQ   2048
#define EMB   2048
#define HEADS 16
#define DHEAD 128
#define MTOT  (BATCH*SEQ)     // 4096
#define NQKV  (3*EMB)         // 6144
#define BHT   (BATCH*HEADS)   // 32
#define KDIM  2048

// ---------------------------------------------------------------------------
// Global scratch
// ---------------------------------------------------------------------------
__device__ float2 g_rope[(size_t)SEQ * 64];

__device__ __nv_bfloat16 g_qhi[(size_t)BHT * SEQ * DHEAD];
__device__ __nv_bfloat16 g_qlo[(size_t)BHT * SEQ * DHEAD];
__device__ __nv_bfloat16 g_khi[(size_t)BHT * SEQ * DHEAD];
__device__ __nv_bfloat16 g_klo[(size_t)BHT * SEQ * DHEAD];
__device__ __nv_bfloat16 g_vhi[(size_t)BHT * SEQ * DHEAD];
__device__ __nv_bfloat16 g_vlo[(size_t)BHT * SEQ * DHEAD];

__device__ __half g_xh16[(size_t)MTOT * EMB];
__device__ __half g_xl16[(size_t)MTOT * EMB];
__device__ __half g_wq16[(size_t)NQKV * KDIM];

__device__ __nv_bfloat16 g_ahi[(size_t)MTOT * EMB];
__device__ __nv_bfloat16 g_alo[(size_t)MTOT * EMB];
__device__ __nv_bfloat16 g_wohi[(size_t)EMB * KDIM];
__device__ __nv_bfloat16 g_wolo[(size_t)EMB * KDIM];

// ---------------------------------------------------------------------------
// PTX helpers (sm_100 BASELINE only)
// ---------------------------------------------------------------------------
__device__ __forceinline__ uint32_t smem_u32(const void* p) {
    uint32_t a;
    asm("{ .reg .u64 t; cvta.to.shared.u64 t, %1; cvt.u32.u64 %0, t; }" : "=r"(a) : "l"(p));
    return a;
}
__device__ __forceinline__ void cp16(uint32_t s, const void* g) {
    asm volatile("cp.async.cg.shared.global [%0], [%1], 16;" :: "r"(s), "l"(g));
}
#define CP_COMMIT() asm volatile("cp.async.commit_group;" ::: "memory")
#define CP_WAIT(N)  asm volatile("cp.async.wait_group %0;" :: "n"(N) : "memory")

__device__ __forceinline__ void ldsm_x4(uint32_t r[4], uint32_t addr) {
    asm volatile("ldmatrix.sync.aligned.m8n8.x4.shared.b16 {%0,%1,%2,%3}, [%4];"
                 : "=r"(r[0]), "=r"(r[1]), "=r"(r[2]), "=r"(r[3]) : "r"(addr));
}
__device__ __forceinline__ void ldsm_x4_t(uint32_t r[4], uint32_t addr) {
    asm volatile("ldmatrix.sync.aligned.m8n8.x4.trans.shared.b16 {%0,%1,%2,%3}, [%4];"
                 : "=r"(r[0]), "=r"(r[1]), "=r"(r[2]), "=r"(r[3]) : "r"(addr));
}
__device__ __forceinline__ void mma_bf16(float c[4], const uint32_t a[4],
                                         uint32_t b0, uint32_t b1) {
    asm volatile("mma.sync.aligned.m16n8k16.row.col.f32.bf16.bf16.f32 "
                 "{%0,%1,%2,%3}, {%4,%5,%6,%7}, {%8,%9}, {%0,%1,%2,%3};"
                 : "+f"(c[0]), "+f"(c[1]), "+f"(c[2]), "+f"(c[3])
                 : "r"(a[0]), "r"(a[1]), "r"(a[2]), "r"(a[3]), "r"(b0), "r"(b1));
}
__device__ __forceinline__ void mma_fp16(float c[4], const uint32_t a[4],
                                         uint32_t b0, uint32_t b1) {
    asm volatile("mma.sync.aligned.m16n8k16.row.col.f32.f16.f16.f32 "
                 "{%0,%1,%2,%3}, {%4,%5,%6,%7}, {%8,%9}, {%0,%1,%2,%3};"
                 : "+f"(c[0]), "+f"(c[1]), "+f"(c[2]), "+f"(c[3])
                 : "r"(a[0]), "r"(a[1]), "r"(a[2]), "r"(a[3]), "r"(b0), "r"(b1));
}
__device__ __forceinline__ float ex2f(float x) {
    float y; asm("ex2.approx.ftz.f32 %0, %1;" : "=f"(y) : "f"(x)); return y;
}
__device__ __forceinline__ uint32_t pack_bf16x2(float a, float b) {
    __nv_bfloat162 t = __floats2bfloat162_rn(a, b);
    return *reinterpret_cast<uint32_t*>(&t);
}
__device__ __forceinline__ uint32_t pack_f16x2(float a, float b) {
    __half2 t = __floats2half2_rn(a, b);
    return *reinterpret_cast<uint32_t*>(&t);
}

// ===========================================================================
// QKV GEMM + fused RoPE epilogue (R13 config: BM=128, warp 32x64, measured
// 550us @ tensor 71%). fp16 2-pass, pass-major order. BK=32, 3 stages.
// ===========================================================================
#define GBKF   32
#define NCHF   (KDIM / GBKF)
#define MATF   8192
#define STAGEF (3 * MATF)
#define GEMMF_SMEM (3 * STAGEF)      // 73728; epi tile 128*132*4=67584 fits

__device__ __forceinline__ void load_stage_f(uint32_t st,
    const __half* __restrict__ Ah, const __half* __restrict__ Al,
    const __half* __restrict__ Bh, int k0, int tid)
{
#pragma unroll
    for (int i = 0; i < 2; i++) {
        int uid = tid + (i << 8);
        int r = uid >> 2, u = uid & 3;
        size_t   goff = (size_t)r * KDIM + k0 + u * 8;
        uint32_t soff = r * 64 + ((u ^ ((r >> 1) & 3)) << 4);
        cp16(st + soff,            Ah + goff);
        cp16(st + MATF + soff,     Al + goff);
        cp16(st + 2 * MATF + soff, Bh + goff);
    }
}

__device__ __forceinline__ void compute_chunk_f(uint32_t st, int lane, int wm, int wn,
                                                float acc[2][8][4])
{
    const int aRow0 = wm * 32 + ((lane >> 3) & 1) * 8 + (lane & 7);
    const int bRow0 = wn * 64 + ((lane >> 4) << 3) + (lane & 7);
    const int au = (lane >> 4);
    const int bu = ((lane >> 3) & 1);
#pragma unroll
    for (int ks = 0; ks < 2; ks++) {
        uint32_t ah[2][4], al[2][4];
#pragma unroll
        for (int mt = 0; mt < 2; mt++) {
            int row = aRow0 + mt * 16;
            int u   = ks * 2 + au;
            uint32_t off = row * 64 + ((u ^ ((row >> 1) & 3)) << 4);
            ldsm_x4(ah[mt], st + off);
            ldsm_x4(al[mt], st + MATF + off);
        }
        uint32_t bh[4][4];
#pragma unroll
        for (int ng = 0; ng < 4; ng++) {
            int row = bRow0 + ng * 16;
            int u   = ks * 2 + bu;
            uint32_t off = row * 64 + ((u ^ ((row >> 1) & 3)) << 4);
            ldsm_x4(bh[ng], st + 2 * MATF + off);
        }
        // pass 1: A-hi (16 MMAs, 16 distinct accumulators)
#pragma unroll
        for (int mt = 0; mt < 2; mt++)
#pragma unroll
            for (int ng = 0; ng < 4; ng++) {
                mma_fp16(acc[mt][ng * 2],     ah[mt], bh[ng][0], bh[ng][1]);
                mma_fp16(acc[mt][ng * 2 + 1], ah[mt], bh[ng][2], bh[ng][3]);
            }
        // pass 2: A-lo
#pragma unroll
        for (int mt = 0; mt < 2; mt++)
#pragma unroll
            for (int ng = 0; ng < 4; ng++) {
                mma_fp16(acc[mt][ng * 2],     al[mt], bh[ng][0], bh[ng][1]);
                mma_fp16(acc[mt][ng * 2 + 1], al[mt], bh[ng][2], bh[ng][3]);
            }
    }
}

__global__ __launch_bounds__(256, 2)
void gemm_qkv_rope_kernel(const __half* __restrict__ Ahi, const __half* __restrict__ Alo,
                          const __half* __restrict__ Bhi, const float* __restrict__ bias,
                          __nv_bfloat16* __restrict__ Qh, __nv_bfloat16* __restrict__ Ql,
                          __nv_bfloat16* __restrict__ Kh, __nv_bfloat16* __restrict__ Kl,
                          __nv_bfloat16* __restrict__ Vh, __nv_bfloat16* __restrict__ Vl)
{
    extern __shared__ __align__(1024) char sm[];
    const uint32_t sbase = smem_u32(sm);
    const int tid  = threadIdx.x;
    const int lane = tid & 31;
    const int wid  = tid >> 5;
    const int wm   = wid & 3;
    const int wn   = wid >> 2;
    const int m0 = blockIdx.y * 128;
    const int n0 = blockIdx.x * 128;

    const __half* Ahb = Ahi + (size_t)m0 * KDIM;
    const __half* Alb = Alo + (size_t)m0 * KDIM;
    const __half* Bhb = Bhi + (size_t)n0 * KDIM;

    float acc[2][8][4];
#pragma unroll
    for (int a = 0; a < 2; a++)
#pragma unroll
        for (int b = 0; b < 8; b++)
#pragma unroll
            for (int c = 0; c < 4; c++) acc[a][b][c] = 0.f;

    load_stage_f(sbase,          Ahb, Alb, Bhb, 0, tid);
    CP_COMMIT();
    load_stage_f(sbase + STAGEF, Ahb, Alb, Bhb, GBKF, tid);
    CP_COMMIT();

    uint32_t stage_off[3] = {0, STAGEF, 2 * STAGEF};
    for (int c = 0; c < NCHF; c++) {
        CP_WAIT(1);
        __syncthreads();
        compute_chunk_f(sbase + stage_off[c % 3], lane, wm, wn, acc);
        if (c + 2 < NCHF)
            load_stage_f(sbase + stage_off[(c + 2) % 3],
                         Ahb, Alb, Bhb, (c + 2) * GBKF, tid);
        CP_COMMIT();
    }

    // ---- fused RoPE epilogue ----
    float* eps = (float*)sm;                 // [128][132] fp32, reuses stage smem
    __syncthreads();

    const int g   = lane >> 2;
    const int tg2 = (lane & 3) * 2;
#pragma unroll
    for (int mt = 0; mt < 2; mt++) {
        int r0 = wm * 32 + mt * 16 + g;
#pragma unroll
        for (int ng = 0; ng < 8; ng++) {
            int col = wn * 64 + ng * 8 + tg2;
            *(float2*)&eps[r0 * 132 + col]       = make_float2(acc[mt][ng][0], acc[mt][ng][1]);
            *(float2*)&eps[(r0 + 8) * 132 + col] = make_float2(acc[mt][ng][2], acc[mt][ng][3]);
        }
    }
    __syncthreads();

    const int mat = n0 >> 11;                // 0=Q, 1=K, 2=V
    const int h   = (n0 & 2047) >> 7;        // head within matrix
    __nv_bfloat16* Hi1; __nv_bfloat16* Lo1;
    if (mat == 0)      { Hi1 = Qh; Lo1 = Ql; }
    else if (mat == 1) { Hi1 = Kh; Lo1 = Kl; }
    else               { Hi1 = Vh; Lo1 = Vl; }

#pragma unroll 4
    for (int p = 0; p < 32; p++) {
        int pid = tid + (p << 8);            // 0..8191
        int r = pid >> 6;                    // tile row 0..127
        int j = pid & 63;                    // rope pair index
        int t = m0 + r;
        int n = t & (SEQ - 1);
        int b = t >> 11;

        float v1 = eps[r * 132 + j]      + bias[n0 + j];
        float v2 = eps[r * 132 + j + 64] + bias[n0 + j + 64];
        float o1, o2;
        if (mat < 2) {
            float2 cssn = g_rope[(n << 6) + j];
            o1 = v1 * cssn.x - v2 * cssn.y;
            o2 = v1 * cssn.y + v2 * cssn.x;
        } else {
            o1 = v1; o2 = v2;
        }
        size_t o = ((size_t)(b * HEADS + h) * SEQ + n) * DHEAD + j;
        float h1 = __bfloat162float(__float2bfloat16(o1));
        float h2 = __bfloat162float(__float2bfloat16(o2));
        Hi1[o]      = __float2bfloat16(o1);
        Lo1[o]      = __float2bfloat16(o1 - h1);
        Hi1[o + 64] = __float2bfloat16(o2);
        Lo1[o + 64] = __float2bfloat16(o2 - h2);
    }
}

// ===========================================================================
// Out-proj GEMM: bf16 3-pass, pass-major order (unchanged; 282us measured).
// ===========================================================================
#define GBK2   32
#define NCH2   (KDIM / GBK2)
#define MATB2  8192
#define STAGE2 (4 * MATB2)
#define GEMM_SMEM (3 * STAGE2)

__device__ __forceinline__ void load_stage2(uint32_t st,
    const __nv_bfloat16* __restrict__ Ah, const __nv_bfloat16* __restrict__ Al,
    const __nv_bfloat16* __restrict__ Bh, const __nv_bfloat16* __restrict__ Bl,
    int k0, int tid)
{
#pragma unroll
    for (int i = 0; i < 2; i++) {
        int uid = tid + (i << 8);
        int r = uid >> 2, u = uid & 3;
        size_t   goff = (size_t)r * KDIM + k0 + u * 8;
        uint32_t soff = r * 64 + ((u ^ ((r >> 1) & 3)) << 4);
        cp16(st + soff,             Ah + goff);
        cp16(st + MATB2 + soff,     Al + goff);
        cp16(st + 2 * MATB2 + soff, Bh + goff);
        cp16(st + 3 * MATB2 + soff, Bl + goff);
    }
}

__device__ __forceinline__ void compute_chunk2(uint32_t st, int lane, int wm, int wn,
                                               float acc[2][8][4])
{
    const int aRow0 = wm * 32 + ((lane >> 3) & 1) * 8 + (lane & 7);
    const int bRow0 = wn * 64 + ((lane >> 4) << 3) + (lane & 7);
    const int au = (lane >> 4);
    const int bu = ((lane >> 3) & 1);
#pragma unroll
    for (int ks = 0; ks < 2; ks++) {
        uint32_t ah[2][4], al[2][4];
#pragma unroll
        for (int mt = 0; mt < 2; mt++) {
            int row = aRow0 + mt * 16;
            int u   = ks * 2 + au;
            uint32_t off = row * 64 + ((u ^ ((row >> 1) & 3)) << 4);
            ldsm_x4(ah[mt], st + off);
            ldsm_x4(al[mt], st + MATB2 + off);
        }
        uint32_t bh[4][4], bl[4][4];
#pragma unroll
        for (int ng = 0; ng < 4; ng++) {
            int row = bRow0 + ng * 16;
            int u   = ks * 2 + bu;
            uint32_t off = row * 64 + ((u ^ ((row >> 1) & 3)) << 4);
            ldsm_x4(bh[ng], st + 2 * MATB2 + off);
            ldsm_x4(bl[ng], st + 3 * MATB2 + off);
        }
#pragma unroll
        for (int mt = 0; mt < 2; mt++)
#pragma unroll
            for (int ng = 0; ng < 4; ng++) {
                mma_bf16(acc[mt][ng * 2],     ah[mt], bh[ng][0], bh[ng][1]);
                mma_bf16(acc[mt][ng * 2 + 1], ah[mt], bh[ng][2], bh[ng][3]);
            }
#pragma unroll
        for (int mt = 0; mt < 2; mt++)
#pragma unroll
            for (int ng = 0; ng < 4; ng++) {
                mma_bf16(acc[mt][ng * 2],     al[mt], bh[ng][0], bh[ng][1]);
                mma_bf16(acc[mt][ng * 2 + 1], al[mt], bh[ng][2], bh[ng][3]);
            }
#pragma unroll
        for (int mt = 0; mt < 2; mt++)
#pragma unroll
            for (int ng = 0; ng < 4; ng++) {
                mma_bf16(acc[mt][ng * 2],     ah[mt], bl[ng][0], bl[ng][1]);
                mma_bf16(acc[mt][ng * 2 + 1], ah[mt], bl[ng][2], bl[ng][3]);
            }
    }
}

__global__ __launch_bounds__(256, 2)
void gemm_mma_kernel(const __nv_bfloat16* __restrict__ Ahi, const __nv_bfloat16* __restrict__ Alo,
                     const __nv_bfloat16* __restrict__ Bhi, const __nv_bfloat16* __restrict__ Blo,
                     const float* __restrict__ bias, float* __restrict__ C, int Nt)
{
    extern __shared__ __align__(1024) char sm[];
    const uint32_t sbase = smem_u32(sm);
    const int tid  = threadIdx.x;
    const int lane = tid & 31;
    const int wid  = tid >> 5;
    const int wm   = wid & 3;
    const int wn   = wid >> 2;
    const int m0 = blockIdx.y * 128;
    const int n0 = blockIdx.x * 128;

    const __nv_bfloat16* Ahb = Ahi + (size_t)m0 * KDIM;
    const __nv_bfloat16* Alb = Alo + (size_t)m0 * KDIM;
    const __nv_bfloat16* Bhb = Bhi + (size_t)n0 * KDIM;
    const __nv_bfloat16* Blb = Blo + (size_t)n0 * KDIM;

    float acc[2][8][4];
#pragma unroll
    for (int a = 0; a < 2; a++)
#pragma unroll
        for (int b = 0; b < 8; b++)
#pragma unroll
            for (int c = 0; c < 4; c++) acc[a][b][c] = 0.f;

    load_stage2(sbase,          Ahb, Alb, Bhb, Blb, 0, tid);
    CP_COMMIT();
    load_stage2(sbase + STAGE2, Ahb, Alb, Bhb, Blb, GBK2, tid);
    CP_COMMIT();

    uint32_t stage_off[3] = {0, STAGE2, 2 * STAGE2};
    for (int c = 0; c < NCH2; c++) {
        CP_WAIT(1);
        __syncthreads();
        compute_chunk2(sbase + stage_off[c % 3], lane, wm, wn, acc);
        if (c + 2 < NCH2)
            load_stage2(sbase + stage_off[(c + 2) % 3],
                        Ahb, Alb, Bhb, Blb, (c + 2) * GBK2, tid);
        CP_COMMIT();
    }

    const int g   = lane >> 2;
    const int tg2 = (lane & 3) * 2;
#pragma unroll
    for (int mt = 0; mt < 2; mt++) {
        int r0 = m0 + wm * 32 + mt * 16 + g;
#pragma unroll
        for (int ng = 0; ng < 8; ng++) {
            int col = n0 + wn * 64 + ng * 8 + tg2;
            float b0 = bias[col], b1 = bias[col + 1];
            float2 v0 = make_float2(acc[mt][ng][0] + b0, acc[mt][ng][1] + b1);
            float2 v1 = make_float2(acc[mt][ng][2] + b0, acc[mt][ng][3] + b1);
            *(float2*)&C[(size_t)r0 * Nt + col]       = v0;
            *(float2*)&C[(size_t)(r0 + 8) * Nt + col] = v1;
        }
    }
}

// ---------------------------------------------------------------------------
// Merged prep: Wqkv trans->fp16 | Wo trans->bf16 hi/lo | rope table | x split
// ---------------------------------------------------------------------------
#define WQ_BLKS ((NQKV/32)*(KDIM/32))     // 12288
#define WO_BLKS ((EMB/32)*(KDIM/32))      // 4096
#define RT_BLKS 512
#define XC_BLKS (MTOT*EMB/4/256)          // 8192
#define PREP_BLKS (WQ_BLKS + WO_BLKS + RT_BLKS + XC_BLKS)

__global__ __launch_bounds__(256)
void prep_all_kernel(const float* __restrict__ Wqkv, __half* __restrict__ Wq16,
                     const float* __restrict__ Wo,
                     __nv_bfloat16* __restrict__ Wohi, __nv_bfloat16* __restrict__ Wolo,
                     const float* __restrict__ X,
                     __half* __restrict__ Xhi, __half* __restrict__ Xlo)
{
    __shared__ float t[32][33];
    const int tid = threadIdx.x;
    const int bx = blockIdx.x;

    if (bx < WQ_BLKS) {
        const int n0 = (bx % (NQKV / 32)) * 32, k0 = (bx / (NQKV / 32)) * 32;
        {
            int row = tid >> 3, c4 = (tid & 7) * 4;
            float4 v = *(const float4*)&Wqkv[(size_t)(k0 + row) * NQKV + n0 + c4];
            t[row][c4] = v.x; t[row][c4 + 1] = v.y; t[row][c4 + 2] = v.z; t[row][c4 + 3] = v.w;
        }
        __syncthreads();
        {
            int n = tid >> 3, kc = (tid & 7) * 4;
            float f0 = t[kc][n], f1 = t[kc + 1][n], f2 = t[kc + 2][n], f3 = t[kc + 3][n];
            size_t o = (size_t)(n0 + n) * KDIM + k0 + kc;
            *(uint2*)&Wq16[o] = make_uint2(pack_f16x2(f0, f1), pack_f16x2(f2, f3));
        }
    } else if (bx < WQ_BLKS + WO_BLKS) {
        const int i = bx - WQ_BLKS;
        const int n0 = (i % (EMB / 32)) * 32, k0 = (i / (EMB / 32)) * 32;
        {
            int row = tid >> 3, c4 = (tid & 7) * 4;
            float4 v = *(const float4*)&Wo[(size_t)(k0 + row) * EMB + n0 + c4];
            t[row][c4] = v.x; t[row][c4 + 1] = v.y; t[row][c4 + 2] = v.z; t[row][c4 + 3] = v.w;
        }
        __syncthreads();
        {
            int n = tid >> 3, kc = (tid & 7) * 4;
            float f0 = t[kc][n], f1 = t[kc + 1][n], f2 = t[kc + 2][n], f3 = t[kc + 3][n];
#define HI(x) __bfloat162float(__float2bfloat16(x))
            uint32_t hp0 = pack_bf16x2(f0, f1), hp1 = pack_bf16x2(f2, f3);
            uint32_t lp0 = pack_bf16x2(f0 - HI(f0), f1 - HI(f1));
            uint32_t lp1 = pack_bf16x2(f2 - HI(f2), f3 - HI(f3));
#undef HI
            size_t o = (size_t)(n0 + n) * KDIM + k0 + kc;
            *(uint2*)&Wohi[o] = make_uint2(hp0, hp1);
            *(uint2*)&Wolo[o] = make_uint2(lp0, lp1);
        }
    } else if (bx < WQ_BLKS + WO_BLKS + RT_BLKS) {
        int idx = (bx - WQ_BLKS - WO_BLKS) * 256 + tid;
        if (idx >= SEQ * 64) return;
        int n = idx >> 6, j = idx & 63;
        float pf = __bfloat162float(__float2bfloat16(
                       (float)pow(10000.0, (double)j * (1.0 / 64.0))));
        float th = __bfloat162float(__float2bfloat16(1.0f / pf));
        float sn, cs;
        sincosf((float)n * th, &sn, &cs);
        g_rope[idx] = make_float2(cs, sn);
    } else {
        int i = (bx - WQ_BLKS - WO_BLKS - RT_BLKS) * 256 + tid;
        if (i >= MTOT * EMB / 4) return;
        float4 v = ((const float4*)X)[i];
        float f[4] = {v.x, v.y, v.z, v.w};
        float h[4];
#pragma unroll
        for (int j = 0; j < 4; j++) h[j] = __half2float(__float2half_rn(f[j]));
        ((uint2*)Xhi)[i] = make_uint2(pack_f16x2(f[0], f[1]), pack_f16x2(f[2], f[3]));
        ((uint2*)Xlo)[i] = make_uint2(pack_f16x2(f[0] - h[0], f[1] - h[1]),
                                      pack_f16x2(f[2] - h[2], f[3] - h[3]));
    }
}

// ---------------------------------------------------------------------------
// Flash attention (unchanged)
// ---------------------------------------------------------------------------
#define FA_QBYTES   32768
#define FA_KVMAT    16384
#define FA_STAGE    (4 * FA_KVMAT)
#define FA_SMEM     (2 * FA_QBYTES + 2 * FA_STAGE)

__device__ __forceinline__ void fa_load_kv(uint32_t st,
    const __nv_bfloat16* kh, const __nv_bfloat16* kl,
    const __nv_bfloat16* vh, const __nv_bfloat16* vl, int tid)
{
#pragma unroll
    for (int i = 0; i < 4; i++) {
        int uid = tid + (i << 8);
        int r = uid >> 4, u = uid & 15;
        uint32_t so = r * 256 + ((u ^ (r & 7)) << 4);
        size_t go = (size_t)r * 128 + u * 8;
        cp16(st + so,                kh + go);
        cp16(st + FA_KVMAT + so,     kl + go);
        cp16(st + 2 * FA_KVMAT + so, vh + go);
        cp16(st + 3 * FA_KVMAT + so, vl + go);
    }
}

__global__ __launch_bounds__(256)
void flash_mma_kernel(const __nv_bfloat16* __restrict__ Qh, const __nv_bfloat16* __restrict__ Ql,
                      const __nv_bfloat16* __restrict__ Kh, const __nv_bfloat16* __restrict__ Kl,
                      const __nv_bfloat16* __restrict__ Vh, const __nv_bfloat16* __restrict__ Vl,
                      __nv_bfloat16* __restrict__ Ohi, __nv_bfloat16* __restrict__ Olo)
{
    extern __shared__ __align__(1024) char sm[];
    const uint32_t sb = smem_u32(sm);
    const int tid = threadIdx.x, lane = tid & 31, w = tid >> 5;
    const int qb = gridDim.x - 1 - blockIdx.x;
    const int bh = blockIdx.y;
    const int row_lo = qb * 128 + w * 16;
    const uint32_t sQh = sb, sQl = sb + FA_QBYTES;
    const uint32_t sKV = sb + 2 * FA_QBYTES;

    {
        const __nv_bfloat16* qhg = Qh + ((size_t)bh * SEQ + qb * 128) * DHEAD;
        const __nv_bfloat16* qlg = Ql + ((size_t)bh * SEQ + qb * 128) * DHEAD;
#pragma unroll
        for (int i = 0; i < 8; i++) {
            int uid = tid + (i << 8);
            int r = uid >> 4, u = uid & 15;
            uint32_t so = r * 256 + ((u ^ (r & 7)) << 4);
            size_t go = (size_t)r * 128 + u * 8;
            cp16(sQh + so, qhg + go);
            cp16(sQl + so, qlg + go);
        }
    }
    const __nv_bfloat16* khb = Kh + (size_t)bh * SEQ * DHEAD;
    const __nv_bfloat16* klb = Kl + (size_t)bh * SEQ * DHEAD;
    const __nv_bfloat16* vhb = Vh + (size_t)bh * SEQ * DHEAD;
    const __nv_bfloat16* vlb = Vl + (size_t)bh * SEQ * DHEAD;

    fa_load_kv(sKV, khb, klb, vhb, vlb, tid);
    CP_COMMIT();

    float O[16][4];
#pragma unroll
    for (int i = 0; i < 16; i++)
#pragma unroll
        for (int j = 0; j < 4; j++) O[i][j] = 0.f;
    float mrow0 = -1e30f, mrow1 = -1e30f, lrow0 = 0.f, lrow1 = 0.f;

    const float SC = 0.08838834764831845f * 1.4426950408889634f;
    const int nkb = 2 * qb + 2;

    for (int kb = 0; kb < nkb; kb++) {
        const uint32_t st = sKV + (kb & 1) * FA_STAGE;
        if (kb + 1 < nkb) {
            fa_load_kv(sKV + ((kb + 1) & 1) * FA_STAGE,
                       khb + (size_t)(kb + 1) * 64 * DHEAD, klb + (size_t)(kb + 1) * 64 * DHEAD,
                       vhb + (size_t)(kb + 1) * 64 * DHEAD, vlb + (size_t)(kb + 1) * 64 * DHEAD, tid);
            CP_COMMIT();
            CP_WAIT(1);
        } else {
            CP_WAIT(0);
        }
        __syncthreads();

        const bool skip = (kb * 64 > row_lo + 15);
        if (!skip) {
            float S[8][4];
#pragma unroll
            for (int i = 0; i < 8; i++)
#pragma unroll
                for (int j = 0; j < 4; j++) S[i][j] = 0.f;

            const int ar = w * 16 + (lane & 7) + ((lane >> 3) & 1) * 8;
            const int br_ = ((lane >> 4) << 3) + (lane & 7);
            const int au = (lane >> 4);
            const int bu = ((lane >> 3) & 1);
#pragma unroll
            for (int ks = 0; ks < 8; ks++) {
                uint32_t qa[4], ql4[4];
                uint32_t aoff = ar * 256 + (((2 * ks + au) ^ (ar & 7)) << 4);
                ldsm_x4(qa, sQh + aoff);
                ldsm_x4(ql4, sQl + aoff);
                uint32_t kh4[4][4], kl4[4][4];
#pragma unroll
                for (int ng = 0; ng < 4; ng++) {
                    int br = ng * 16 + br_;
                    uint32_t boff = br * 256 + (((2 * ks + bu) ^ (br & 7)) << 4);
                    ldsm_x4(kh4[ng], st + boff);
                    ldsm_x4(kl4[ng], st + FA_KVMAT + boff);
                }
#pragma unroll
                for (int ng = 0; ng < 4; ng++) {
                    mma_bf16(S[2 * ng],     qa, kh4[ng][0], kh4[ng][1]);
                    mma_bf16(S[2 * ng + 1], qa, kh4[ng][2], kh4[ng][3]);
                }
#pragma unroll
                for (int ng = 0; ng < 4; ng++) {
                    mma_bf16(S[2 * ng],     ql4, kh4[ng][0], kh4[ng][1]);
                    mma_bf16(S[2 * ng + 1], ql4, kh4[ng][2], kh4[ng][3]);
                }
#pragma unroll
                for (int ng = 0; ng < 4; ng++) {
                    mma_bf16(S[2 * ng],     qa, kl4[ng][0], kl4[ng][1]);
                    mma_bf16(S[2 * ng + 1], qa, kl4[ng][2], kl4[ng][3]);
                }
            }

            const int r0 = row_lo + (lane >> 2), r1 = r0 + 8;
            const int c00 = kb * 64 + (lane & 3) * 2;
            float m0p = -1e30f, m1p = -1e30f;
#pragma unroll
            for (int nt = 0; nt < 8; nt++) {
                int c = c00 + nt * 8;
#pragma unroll
                for (int j = 0; j < 4; j++) {
                    int col = c + (j & 1);
                    int row = (j < 2) ? r0 : r1;
                    float s = S[nt][j] * SC;
                    if (col > row) s = -1e30f;
                    S[nt][j] = s;
                }
                m0p = fmaxf(m0p, fmaxf(S[nt][0], S[nt][1]));
                m1p = fmaxf(m1p, fmaxf(S[nt][2], S[nt][3]));
            }
            m0p = fmaxf(m0p, __shfl_xor_sync(0xffffffffu, m0p, 1));
            m0p = fmaxf(m0p, __shfl_xor_sync(0xffffffffu, m0p, 2));
            m1p = fmaxf(m1p, __shfl_xor_sync(0xffffffffu, m1p, 1));
            m1p = fmaxf(m1p, __shfl_xor_sync(0xffffffffu, m1p, 2));
            const float mn0 = fmaxf(mrow0, m0p), mn1 = fmaxf(mrow1, m1p);
            const float a0 = ex2f(mrow0 - mn0), a1 = ex2f(mrow1 - mn1);
            mrow0 = mn0; mrow1 = mn1;
            float ps0 = 0.f, ps1 = 0.f;
#pragma unroll
            for (int nt = 0; nt < 8; nt++) {
                S[nt][0] = ex2f(S[nt][0] - mn0);
                S[nt][1] = ex2f(S[nt][1] - mn0);
                S[nt][2] = ex2f(S[nt][2] - mn1);
                S[nt][3] = ex2f(S[nt][3] - mn1);
                ps0 += S[nt][0] + S[nt][1];
                ps1 += S[nt][2] + S[nt][3];
            }
            lrow0 = lrow0 * a0 + ps0;
            lrow1 = lrow1 * a1 + ps1;
#pragma unroll
            for (int dt = 0; dt < 16; dt++) {
                O[dt][0] *= a0; O[dt][1] *= a0;
                O[dt][2] *= a1; O[dt][3] *= a1;
            }

            const int vr_ = (lane & 7) + ((lane >> 3) & 1) * 8;
            const int vu_ = (lane >> 4);
#pragma unroll
            for (int ks2 = 0; ks2 < 4; ks2++) {
                uint32_t ph[4], pl[4];
                {
                    float p0 = S[2 * ks2][0], p1 = S[2 * ks2][1];
                    float p2 = S[2 * ks2][2], p3 = S[2 * ks2][3];
                    float p4 = S[2 * ks2 + 1][0], p5 = S[2 * ks2 + 1][1];
                    float p6 = S[2 * ks2 + 1][2], p7 = S[2 * ks2 + 1][3];
                    ph[0] = pack_bf16x2(p0, p1);
                    ph[1] = pack_bf16x2(p2, p3);
                    ph[2] = pack_bf16x2(p4, p5);
                    ph[3] = pack_bf16x2(p6, p7);
#define RES(x) ((x) - __bfloat162float(__float2bfloat16(x)))
                    pl[0] = pack_bf16x2(RES(p0), RES(p1));
                    pl[1] = pack_bf16x2(RES(p2), RES(p3));
                    pl[2] = pack_bf16x2(RES(p4), RES(p5));
                    pl[3] = pack_bf16x2(RES(p6), RES(p7));
#undef RES
                }
                int vr = ks2 * 16 + vr_;
#pragma unroll
                for (int dp = 0; dp < 8; dp++) {
                    uint32_t voff = vr * 256 + (((dp * 2 + vu_) ^ (vr & 7)) << 4);
                    uint32_t vh4[4], vl4[4];
                    ldsm_x4_t(vh4, st + 2 * FA_KVMAT + voff);
                    ldsm_x4_t(vl4, st + 3 * FA_KVMAT + voff);
                    mma_bf16(O[2 * dp],     ph, vh4[0], vh4[1]);
                    mma_bf16(O[2 * dp + 1], ph, vh4[2], vh4[3]);
                    mma_bf16(O[2 * dp],     pl, vh4[0], vh4[1]);
                    mma_bf16(O[2 * dp + 1], pl, vh4[2], vh4[3]);
                    mma_bf16(O[2 * dp],     ph, vl4[0], vl4[1]);
                    mma_bf16(O[2 * dp + 1], ph, vl4[2], vl4[3]);
                }
            }
        }
        __syncthreads();
    }

    float l0 = lrow0;
    l0 += __shfl_xor_sync(0xffffffffu, l0, 1);
    l0 += __shfl_xor_sync(0xffffffffu, l0, 2);
    float l1 = lrow1;
    l1 += __shfl_xor_sync(0xffffffffu, l1, 1);
    l1 += __shfl_xor_sync(0xffffffffu, l1, 2);
    const float inv0 = 1.0f / l0, inv1 = 1.0f / l1;

    const int b = bh >> 4, h = bh & 15;
    const int n0r = row_lo + (lane >> 2);
    size_t base0 = ((size_t)(b * SEQ + n0r)) * EMB + h * DHEAD + (lane & 3) * 2;
    size_t base1 = base0 + (size_t)8 * EMB;
#pragma unroll
    for (int dt = 0; dt < 16; dt++) {
        float x0 = O[dt][0] * inv0, x1 = O[dt][1] * inv0;
        float x2 = O[dt][2] * inv1, x3 = O[dt][3] * inv1;
        float h0 = __bfloat162float(__float2bfloat16(x0));
        float h1 = __bfloat162float(__float2bfloat16(x1));
        float h2 = __bfloat162float(__float2bfloat16(x2));
        float h3 = __bfloat162float(__float2bfloat16(x3));
        *(uint32_t*)&Ohi[base0 + dt * 8] = pack_bf16x2(x0, x1);
        *(uint32_t*)&Olo[base0 + dt * 8] = pack_bf16x2(x0 - h0, x1 - h1);
        *(uint32_t*)&Ohi[base1 + dt * 8] = pack_bf16x2(x2, x3);
        *(uint32_t*)&Olo[base1 + dt * 8] = pack_bf16x2(x2 - h2, x3 - h3);
    }
}

// ---------------------------------------------------------------------------
// Launch
// ---------------------------------------------------------------------------
extern "C" void kernel_launch(void* const* d_in, const int* in_sizes, int n_in,
                              void* d_out, int out_size)
{
    const float* x    = (const float*)d_in[0];
    const float* Wqkv = (const float*)d_in[1];
    const float* bqkv = (const float*)d_in[2];
    const float* Wo   = (const float*)d_in[3];
    const float* bo   = (const float*)d_in[4];
    float* out = (float*)d_out;
    (void)in_sizes; (void)n_in; (void)out_size;

    __nv_bfloat16 *qhi, *qlo, *khi, *klo, *vhi, *vlo, *ahi, *alo, *wohi, *wolo;
    __half *xh16, *xl16, *wq16;
    cudaGetSymbolAddress((void**)&qhi,  g_qhi);
    cudaGetSymbolAddress((void**)&qlo,  g_qlo);
    cudaGetSymbolAddress((void**)&khi,  g_khi);
    cudaGetSymbolAddress((void**)&klo,  g_klo);
    cudaGetSymbolAddress((void**)&vhi,  g_vhi);
    cudaGetSymbolAddress((void**)&vlo,  g_vlo);
    cudaGetSymbolAddress((void**)&ahi,  g_ahi);
    cudaGetSymbolAddress((void**)&alo,  g_alo);
    cudaGetSymbolAddress((void**)&wohi, g_wohi);
    cudaGetSymbolAddress((void**)&wolo, g_wolo);
    cudaGetSymbolAddress((void**)&xh16, g_xh16);
    cudaGetSymbolAddress((void**)&xl16, g_xl16);
    cudaGetSymbolAddress((void**)&wq16, g_wq16);

    cudaFuncSetAttribute(gemm_qkv_rope_kernel,
                         cudaFuncAttributeMaxDynamicSharedMemorySize, GEMMF_SMEM);
    cudaFuncSetAttribute(gemm_mma_kernel,
                         cudaFuncAttributeMaxDynamicSharedMemorySize, GEMM_SMEM);
    cudaFuncSetAttribute(flash_mma_kernel,
                         cudaFuncAttributeMaxDynamicSharedMemorySize, FA_SMEM);

    // 1) merged prep (one launch)
    prep_all_kernel<<<PREP_BLKS, 256>>>(Wqkv, wq16, Wo, wohi, wolo, x, xh16, xl16);

    // 2) QKV projection + fused RoPE/split (R13 config: BM=128)
    gemm_qkv_rope_kernel<<<dim3(NQKV / 128, MTOT / 128), 256, GEMMF_SMEM>>>(
        xh16, xl16, wq16, bqkv, qhi, qlo, khi, klo, vhi, vlo);

    // 3) Flash attention -> out-proj A hi/lo directly
    flash_mma_kernel<<<dim3(SEQ / 128, BHT), 256, FA_SMEM>>>(
        qhi, qlo, khi, klo, vhi, vlo, ahi, alo);

    // 4) Output projection — bf16 3-pass
    gemm_mma_kernel<<<dim3(EMB / 128, MTOT / 128), 256, GEMM_SMEM>>>(
        ahi, alo, wohi, wolo, bo, out, EMB);
}

// round 17
// speedup vs baseline: 1.0984x; 1.0166x over previous
#include <cuda_runtime.h>
#include <cuda_bf16.h>
#include <cuda_fp16.h>
#include <math.h>
#include <float.h>
#include <stdint.h>

// ---------------------------------------------------------------------------
// Problem constants
// ---------------------------------------------------------------------------
#define BATCH 2
#define SEQ   2048
#define EMB   2048
#define HEADS 16
#define DHEAD 128
#define MTOT  (BATCH*SEQ)     // 4096
#define NQKV  (3*EMB)         // 6144
#define BHT   (BATCH*HEADS)   // 32
#define KDIM  2048

// ---------------------------------------------------------------------------
// Global scratch
// ---------------------------------------------------------------------------
__device__ float2 g_rope[(size_t)SEQ * 64];

__device__ __nv_bfloat16 g_qhi[(size_t)BHT * SEQ * DHEAD];
__device__ __nv_bfloat16 g_qlo[(size_t)BHT * SEQ * DHEAD];
__device__ __nv_bfloat16 g_khi[(size_t)BHT * SEQ * DHEAD];
__device__ __nv_bfloat16 g_klo[(size_t)BHT * SEQ * DHEAD];
__device__ __nv_bfloat16 g_vhi[(size_t)BHT * SEQ * DHEAD];
__device__ __nv_bfloat16 g_vlo[(size_t)BHT * SEQ * DHEAD];

__device__ __half g_xh16[(size_t)MTOT * EMB];
__device__ __half g_xl16[(size_t)MTOT * EMB];
__device__ __half g_wq16[(size_t)NQKV * KDIM];

__device__ __nv_bfloat16 g_ahi[(size_t)MTOT * EMB];
__device__ __nv_bfloat16 g_alo[(size_t)MTOT * EMB];
__device__ __nv_bfloat16 g_wohi[(size_t)EMB * KDIM];
__device__ __nv_bfloat16 g_wolo[(size_t)EMB * KDIM];

// ---------------------------------------------------------------------------
// PTX helpers (sm_100 BASELINE only)
// ---------------------------------------------------------------------------
__device__ __forceinline__ uint32_t smem_u32(const void* p) {
    uint32_t a;
    asm("{ .reg .u64 t; cvta.to.shared.u64 t, %1; cvt.u32.u64 %0, t; }" : "=r"(a) : "l"(p));
    return a;
}
__device__ __forceinline__ void cp16(uint32_t s, const void* g) {
    asm volatile("cp.async.cg.shared.global [%0], [%1], 16;" :: "r"(s), "l"(g));
}
#define CP_COMMIT() asm volatile("cp.async.commit_group;" ::: "memory")
#define CP_WAIT(N)  asm volatile("cp.async.wait_group %0;" :: "n"(N) : "memory")

__device__ __forceinline__ void ldsm_x4(uint32_t r[4], uint32_t addr) {
    asm volatile("ldmatrix.sync.aligned.m8n8.x4.shared.b16 {%0,%1,%2,%3}, [%4];"
                 : "=r"(r[0]), "=r"(r[1]), "=r"(r[2]), "=r"(r[3]) : "r"(addr));
}
__device__ __forceinline__ void ldsm_x4_t(uint32_t r[4], uint32_t addr) {
    asm volatile("ldmatrix.sync.aligned.m8n8.x4.trans.shared.b16 {%0,%1,%2,%3}, [%4];"
                 : "=r"(r[0]), "=r"(r[1]), "=r"(r[2]), "=r"(r[3]) : "r"(addr));
}
__device__ __forceinline__ void mma_bf16(float c[4], const uint32_t a[4],
                                         uint32_t b0, uint32_t b1) {
    asm volatile("mma.sync.aligned.m16n8k16.row.col.f32.bf16.bf16.f32 "
                 "{%0,%1,%2,%3}, {%4,%5,%6,%7}, {%8,%9}, {%0,%1,%2,%3};"
                 : "+f"(c[0]), "+f"(c[1]), "+f"(c[2]), "+f"(c[3])
                 : "r"(a[0]), "r"(a[1]), "r"(a[2]), "r"(a[3]), "r"(b0), "r"(b1));
}
__device__ __forceinline__ void mma_fp16(float c[4], const uint32_t a[4],
                                         uint32_t b0, uint32_t b1) {
    asm volatile("mma.sync.aligned.m16n8k16.row.col.f32.f16.f16.f32 "
                 "{%0,%1,%2,%3}, {%4,%5,%6,%7}, {%8,%9}, {%0,%1,%2,%3};"
                 : "+f"(c[0]), "+f"(c[1]), "+f"(c[2]), "+f"(c[3])
                 : "r"(a[0]), "r"(a[1]), "r"(a[2]), "r"(a[3]), "r"(b0), "r"(b1));
}
__device__ __forceinline__ float ex2f(float x) {
    float y; asm("ex2.approx.ftz.f32 %0, %1;" : "=f"(y) : "f"(x)); return y;
}
__device__ __forceinline__ uint32_t pack_bf16x2(float a, float b) {
    __nv_bfloat162 t = __floats2bfloat162_rn(a, b);
    return *reinterpret_cast<uint32_t*>(&t);
}
__device__ __forceinline__ uint32_t pack_f16x2(float a, float b) {
    __half2 t = __floats2half2_rn(a, b);
    return *reinterpret_cast<uint32_t*>(&t);
}

// ===========================================================================
// QKV GEMM + fused RoPE epilogue. fp16 2-pass, pass-major order.
// BM=128 (R13 measured-best), BK=32, NOW 4 stages (96KB, 2 CTA/SM),
// prefetch distance 3, and vectorized (uint32) epilogue stores.
// ===========================================================================
#define GBKF   32
#define NCHF   (KDIM / GBKF)
#define MATF   8192
#define STAGEF (3 * MATF)            // 24576
#define GEMMF_SMEM (4 * STAGEF)      // 98304; epi tile 128*132*4=67584 fits

__device__ __forceinline__ void load_stage_f(uint32_t st,
    const __half* __restrict__ Ah, const __half* __restrict__ Al,
    const __half* __restrict__ Bh, int k0, int tid)
{
#pragma unroll
    for (int i = 0; i < 2; i++) {
        int uid = tid + (i << 8);
        int r = uid >> 2, u = uid & 3;
        size_t   goff = (size_t)r * KDIM + k0 + u * 8;
        uint32_t soff = r * 64 + ((u ^ ((r >> 1) & 3)) << 4);
        cp16(st + soff,            Ah + goff);
        cp16(st + MATF + soff,     Al + goff);
        cp16(st + 2 * MATF + soff, Bh + goff);
    }
}

__device__ __forceinline__ void compute_chunk_f(uint32_t st, int lane, int wm, int wn,
                                                float acc[2][8][4])
{
    const int aRow0 = wm * 32 + ((lane >> 3) & 1) * 8 + (lane & 7);
    const int bRow0 = wn * 64 + ((lane >> 4) << 3) + (lane & 7);
    const int au = (lane >> 4);
    const int bu = ((lane >> 3) & 1);
#pragma unroll
    for (int ks = 0; ks < 2; ks++) {
        uint32_t ah[2][4], al[2][4];
#pragma unroll
        for (int mt = 0; mt < 2; mt++) {
            int row = aRow0 + mt * 16;
            int u   = ks * 2 + au;
            uint32_t off = row * 64 + ((u ^ ((row >> 1) & 3)) << 4);
            ldsm_x4(ah[mt], st + off);
            ldsm_x4(al[mt], st + MATF + off);
        }
        uint32_t bh[4][4];
#pragma unroll
        for (int ng = 0; ng < 4; ng++) {
            int row = bRow0 + ng * 16;
            int u   = ks * 2 + bu;
            uint32_t off = row * 64 + ((u ^ ((row >> 1) & 3)) << 4);
            ldsm_x4(bh[ng], st + 2 * MATF + off);
        }
        // pass 1: A-hi (16 MMAs, 16 distinct accumulators)
#pragma unroll
        for (int mt = 0; mt < 2; mt++)
#pragma unroll
            for (int ng = 0; ng < 4; ng++) {
                mma_fp16(acc[mt][ng * 2],     ah[mt], bh[ng][0], bh[ng][1]);
                mma_fp16(acc[mt][ng * 2 + 1], ah[mt], bh[ng][2], bh[ng][3]);
            }
        // pass 2: A-lo
#pragma unroll
        for (int mt = 0; mt < 2; mt++)
#pragma unroll
            for (int ng = 0; ng < 4; ng++) {
                mma_fp16(acc[mt][ng * 2],     al[mt], bh[ng][0], bh[ng][1]);
                mma_fp16(acc[mt][ng * 2 + 1], al[mt], bh[ng][2], bh[ng][3]);
            }
    }
}

__global__ __launch_bounds__(256, 2)
void gemm_qkv_rope_kernel(const __half* __restrict__ Ahi, const __half* __restrict__ Alo,
                          const __half* __restrict__ Bhi, const float* __restrict__ bias,
                          __nv_bfloat16* __restrict__ Qh, __nv_bfloat16* __restrict__ Ql,
                          __nv_bfloat16* __restrict__ Kh, __nv_bfloat16* __restrict__ Kl,
                          __nv_bfloat16* __restrict__ Vh, __nv_bfloat16* __restrict__ Vl)
{
    extern __shared__ __align__(1024) char sm[];
    const uint32_t sbase = smem_u32(sm);
    const int tid  = threadIdx.x;
    const int lane = tid & 31;
    const int wid  = tid >> 5;
    const int wm   = wid & 3;
    const int wn   = wid >> 2;
    const int m0 = blockIdx.y * 128;
    const int n0 = blockIdx.x * 128;

    const __half* Ahb = Ahi + (size_t)m0 * KDIM;
    const __half* Alb = Alo + (size_t)m0 * KDIM;
    const __half* Bhb = Bhi + (size_t)n0 * KDIM;

    float acc[2][8][4];
#pragma unroll
    for (int a = 0; a < 2; a++)
#pragma unroll
        for (int b = 0; b < 8; b++)
#pragma unroll
            for (int c = 0; c < 4; c++) acc[a][b][c] = 0.f;

    // prologue: stages 0,1,2 (prefetch distance 3)
    load_stage_f(sbase,              Ahb, Alb, Bhb, 0, tid);
    CP_COMMIT();
    load_stage_f(sbase + STAGEF,     Ahb, Alb, Bhb, GBKF, tid);
    CP_COMMIT();
    load_stage_f(sbase + 2 * STAGEF, Ahb, Alb, Bhb, 2 * GBKF, tid);
    CP_COMMIT();

    for (int c = 0; c < NCHF; c++) {
        CP_WAIT(2);                  // chunk c complete (c+1, c+2 may pend)
        __syncthreads();             // visibility + guards reuse of stage (c+3)%4
        compute_chunk_f(sbase + (c & 3) * STAGEF, lane, wm, wn, acc);
        if (c + 3 < NCHF)
            load_stage_f(sbase + ((c + 3) & 3) * STAGEF,
                         Ahb, Alb, Bhb, (c + 3) * GBKF, tid);
        CP_COMMIT();
    }

    // ---- fused RoPE epilogue (vectorized stores) ----
    float* eps = (float*)sm;                 // [128][132] fp32, reuses stage smem
    __syncthreads();

    const int g   = lane >> 2;
    const int tg2 = (lane & 3) * 2;
#pragma unroll
    for (int mt = 0; mt < 2; mt++) {
        int r0 = wm * 32 + mt * 16 + g;
#pragma unroll
        for (int ng = 0; ng < 8; ng++) {
            int col = wn * 64 + ng * 8 + tg2;
            *(float2*)&eps[r0 * 132 + col]       = make_float2(acc[mt][ng][0], acc[mt][ng][1]);
            *(float2*)&eps[(r0 + 8) * 132 + col] = make_float2(acc[mt][ng][2], acc[mt][ng][3]);
        }
    }
    __syncthreads();

    const int mat = n0 >> 11;                // 0=Q, 1=K, 2=V
    const int h   = (n0 & 2047) >> 7;        // head within matrix
    __nv_bfloat16* Hi1; __nv_bfloat16* Lo1;
    if (mat == 0)      { Hi1 = Qh; Lo1 = Ql; }
    else if (mat == 1) { Hi1 = Kh; Lo1 = Kl; }
    else               { Hi1 = Vh; Lo1 = Vl; }

    // Each thread handles 2 consecutive rope pairs: j0, j0+1 (and +64 halves).
    // 128 rows x 32 pair-groups = 4096 iterations / 256 threads = 16.
#pragma unroll 4
    for (int p = 0; p < 16; p++) {
        int pid = tid + (p << 8);            // 0..4095
        int r  = pid >> 5;                   // tile row 0..127
        int j0 = (pid & 31) * 2;             // even rope index
        int t = m0 + r;
        int n = t & (SEQ - 1);
        int b = t >> 11;

        float2 va = *(float2*)&eps[r * 132 + j0];
        float2 vb = *(float2*)&eps[r * 132 + j0 + 64];
        float v1a = va.x + bias[n0 + j0];
        float v1b = va.y + bias[n0 + j0 + 1];
        float v2a = vb.x + bias[n0 + j0 + 64];
        float v2b = vb.y + bias[n0 + j0 + 65];

        float o1a, o2a, o1b, o2b;
        if (mat < 2) {
            float4 tr = *(const float4*)(g_rope + ((size_t)n << 6) + j0);
            o1a = v1a * tr.x - v2a * tr.y;
            o2a = v1a * tr.y + v2a * tr.x;
            o1b = v1b * tr.z - v2b * tr.w;
            o2b = v1b * tr.w + v2b * tr.z;
        } else {
            o1a = v1a; o2a = v2a; o1b = v1b; o2b = v2b;
        }
        size_t o = ((size_t)(b * HEADS + h) * SEQ + n) * DHEAD + j0;
        float h1a = __bfloat162float(__float2bfloat16(o1a));
        float h1b = __bfloat162float(__float2bfloat16(o1b));
        float h2a = __bfloat162float(__float2bfloat16(o2a));
        float h2b = __bfloat162float(__float2bfloat16(o2b));
        *(uint32_t*)&Hi1[o]      = pack_bf16x2(o1a, o1b);
        *(uint32_t*)&Lo1[o]      = pack_bf16x2(o1a - h1a, o1b - h1b);
        *(uint32_t*)&Hi1[o + 64] = pack_bf16x2(o2a, o2b);
        *(uint32_t*)&Lo1[o + 64] = pack_bf16x2(o2a - h2a, o2b - h2b);
    }
}

// ===========================================================================
// Out-proj GEMM: bf16 3-pass, pass-major order (unchanged; 284us measured).
// ===========================================================================
#define GBK2   32
#define NCH2   (KDIM / GBK2)
#define MATB2  8192
#define STAGE2 (4 * MATB2)
#define GEMM_SMEM (3 * STAGE2)

__device__ __forceinline__ void load_stage2(uint32_t st,
    const __nv_bfloat16* __restrict__ Ah, const __nv_bfloat16* __restrict__ Al,
    const __nv_bfloat16* __restrict__ Bh, const __nv_bfloat16* __restrict__ Bl,
    int k0, int tid)
{
#pragma unroll
    for (int i = 0; i < 2; i++) {
        int uid = tid + (i << 8);
        int r = uid >> 2, u = uid & 3;
        size_t   goff = (size_t)r * KDIM + k0 + u * 8;
        uint32_t soff = r * 64 + ((u ^ ((r >> 1) & 3)) << 4);
        cp16(st + soff,             Ah + goff);
        cp16(st + MATB2 + soff,     Al + goff);
        cp16(st + 2 * MATB2 + soff, Bh + goff);
        cp16(st + 3 * MATB2 + soff, Bl + goff);
    }
}

__device__ __forceinline__ void compute_chunk2(uint32_t st, int lane, int wm, int wn,
                                               float acc[2][8][4])
{
    const int aRow0 = wm * 32 + ((lane >> 3) & 1) * 8 + (lane & 7);
    const int bRow0 = wn * 64 + ((lane >> 4) << 3) + (lane & 7);
    const int au = (lane >> 4);
    const int bu = ((lane >> 3) & 1);
#pragma unroll
    for (int ks = 0; ks < 2; ks++) {
        uint32_t ah[2][4], al[2][4];
#pragma unroll
        for (int mt = 0; mt < 2; mt++) {
            int row = aRow0 + mt * 16;
            int u   = ks * 2 + au;
            uint32_t off = row * 64 + ((u ^ ((row >> 1) & 3)) << 4);
            ldsm_x4(ah[mt], st + off);
            ldsm_x4(al[mt], st + MATB2 + off);
        }
        uint32_t bh[4][4], bl[4][4];
#pragma unroll
        for (int ng = 0; ng < 4; ng++) {
            int row = bRow0 + ng * 16;
            int u   = ks * 2 + bu;
            uint32_t off = row * 64 + ((u ^ ((row >> 1) & 3)) << 4);
            ldsm_x4(bh[ng], st + 2 * MATB2 + off);
            ldsm_x4(bl[ng], st + 3 * MATB2 + off);
        }
#pragma unroll
        for (int mt = 0; mt < 2; mt++)
#pragma unroll
            for (int ng = 0; ng < 4; ng++) {
                mma_bf16(acc[mt][ng * 2],     ah[mt], bh[ng][0], bh[ng][1]);
                mma_bf16(acc[mt][ng * 2 + 1], ah[mt], bh[ng][2], bh[ng][3]);
            }
#pragma unroll
        for (int mt = 0; mt < 2; mt++)
#pragma unroll
            for (int ng = 0; ng < 4; ng++) {
                mma_bf16(acc[mt][ng * 2],     al[mt], bh[ng][0], bh[ng][1]);
                mma_bf16(acc[mt][ng * 2 + 1], al[mt], bh[ng][2], bh[ng][3]);
            }
#pragma unroll
        for (int mt = 0; mt < 2; mt++)
#pragma unroll
            for (int ng = 0; ng < 4; ng++) {
                mma_bf16(acc[mt][ng * 2],     ah[mt], bl[ng][0], bl[ng][1]);
                mma_bf16(acc[mt][ng * 2 + 1], ah[mt], bl[ng][2], bl[ng][3]);
            }
    }
}

__global__ __launch_bounds__(256, 2)
void gemm_mma_kernel(const __nv_bfloat16* __restrict__ Ahi, const __nv_bfloat16* __restrict__ Alo,
                     const __nv_bfloat16* __restrict__ Bhi, const __nv_bfloat16* __restrict__ Blo,
                     const float* __restrict__ bias, float* __restrict__ C, int Nt)
{
    extern __shared__ __align__(1024) char sm[];
    const uint32_t sbase = smem_u32(sm);
    const int tid  = threadIdx.x;
    const int lane = tid & 31;
    const int wid  = tid >> 5;
    const int wm   = wid & 3;
    const int wn   = wid >> 2;
    const int m0 = blockIdx.y * 128;
    const int n0 = blockIdx.x * 128;

    const __nv_bfloat16* Ahb = Ahi + (size_t)m0 * KDIM;
    const __nv_bfloat16* Alb = Alo + (size_t)m0 * KDIM;
    const __nv_bfloat16* Bhb = Bhi + (size_t)n0 * KDIM;
    const __nv_bfloat16* Blb = Blo + (size_t)n0 * KDIM;

    float acc[2][8][4];
#pragma unroll
    for (int a = 0; a < 2; a++)
#pragma unroll
        for (int b = 0; b < 8; b++)
#pragma unroll
            for (int c = 0; c < 4; c++) acc[a][b][c] = 0.f;

    load_stage2(sbase,          Ahb, Alb, Bhb, Blb, 0, tid);
    CP_COMMIT();
    load_stage2(sbase + STAGE2, Ahb, Alb, Bhb, Blb, GBK2, tid);
    CP_COMMIT();

    uint32_t stage_off[3] = {0, STAGE2, 2 * STAGE2};
    for (int c = 0; c < NCH2; c++) {
        CP_WAIT(1);
        __syncthreads();
        compute_chunk2(sbase + stage_off[c % 3], lane, wm, wn, acc);
        if (c + 2 < NCH2)
            load_stage2(sbase + stage_off[(c + 2) % 3],
                        Ahb, Alb, Bhb, Blb, (c + 2) * GBK2, tid);
        CP_COMMIT();
    }

    const int g   = lane >> 2;
    const int tg2 = (lane & 3) * 2;
#pragma unroll
    for (int mt = 0; mt < 2; mt++) {
        int r0 = m0 + wm * 32 + mt * 16 + g;
#pragma unroll
        for (int ng = 0; ng < 8; ng++) {
            int col = n0 + wn * 64 + ng * 8 + tg2;
            float b0 = bias[col], b1 = bias[col + 1];
            float2 v0 = make_float2(acc[mt][ng][0] + b0, acc[mt][ng][1] + b1);
            float2 v1 = make_float2(acc[mt][ng][2] + b0, acc[mt][ng][3] + b1);
            *(float2*)&C[(size_t)r0 * Nt + col]       = v0;
            *(float2*)&C[(size_t)(r0 + 8) * Nt + col] = v1;
        }
    }
}

// ---------------------------------------------------------------------------
// Merged prep: Wqkv trans->fp16 | Wo trans->bf16 hi/lo | rope table | x split
// ---------------------------------------------------------------------------
#define WQ_BLKS ((NQKV/32)*(KDIM/32))     // 12288
#define WO_BLKS ((EMB/32)*(KDIM/32))      // 4096
#define RT_BLKS 512
#define XC_BLKS (MTOT*EMB/4/256)          // 8192
#define PREP_BLKS (WQ_BLKS + WO_BLKS + RT_BLKS + XC_BLKS)

__global__ __launch_bounds__(256)
void prep_all_kernel(const float* __restrict__ Wqkv, __half* __restrict__ Wq16,
                     const float* __restrict__ Wo,
                     __nv_bfloat16* __restrict__ Wohi, __nv_bfloat16* __restrict__ Wolo,
                     const float* __restrict__ X,
                     __half* __restrict__ Xhi, __half* __restrict__ Xlo)
{
    __shared__ float t[32][33];
    const int tid = threadIdx.x;
    const int bx = blockIdx.x;

    if (bx < WQ_BLKS) {
        const int n0 = (bx % (NQKV / 32)) * 32, k0 = (bx / (NQKV / 32)) * 32;
        {
            int row = tid >> 3, c4 = (tid & 7) * 4;
            float4 v = *(const float4*)&Wqkv[(size_t)(k0 + row) * NQKV + n0 + c4];
            t[row][c4] = v.x; t[row][c4 + 1] = v.y; t[row][c4 + 2] = v.z; t[row][c4 + 3] = v.w;
        }
        __syncthreads();
        {
            int n = tid >> 3, kc = (tid & 7) * 4;
            float f0 = t[kc][n], f1 = t[kc + 1][n], f2 = t[kc + 2][n], f3 = t[kc + 3][n];
            size_t o = (size_t)(n0 + n) * KDIM + k0 + kc;
            *(uint2*)&Wq16[o] = make_uint2(pack_f16x2(f0, f1), pack_f16x2(f2, f3));
        }
    } else if (bx < WQ_BLKS + WO_BLKS) {
        const int i = bx - WQ_BLKS;
        const int n0 = (i % (EMB / 32)) * 32, k0 = (i / (EMB / 32)) * 32;
        {
            int row = tid >> 3, c4 = (tid & 7) * 4;
            float4 v = *(const float4*)&Wo[(size_t)(k0 + row) * EMB + n0 + c4];
            t[row][c4] = v.x; t[row][c4 + 1] = v.y; t[row][c4 + 2] = v.z; t[row][c4 + 3] = v.w;
        }
        __syncthreads();
        {
            int n = tid >> 3, kc = (tid & 7) * 4;
            float f0 = t[kc][n], f1 = t[kc + 1][n], f2 = t[kc + 2][n], f3 = t[kc + 3][n];
#define HI(x) __bfloat162float(__float2bfloat16(x))
            uint32_t hp0 = pack_bf16x2(f0, f1), hp1 = pack_bf16x2(f2, f3);
            uint32_t lp0 = pack_bf16x2(f0 - HI(f0), f1 - HI(f1));
            uint32_t lp1 = pack_bf16x2(f2 - HI(f2), f3 - HI(f3));
#undef HI
            size_t o = (size_t)(n0 + n) * KDIM + k0 + kc;
            *(uint2*)&Wohi[o] = make_uint2(hp0, hp1);
            *(uint2*)&Wolo[o] = make_uint2(lp0, lp1);
        }
    } else if (bx < WQ_BLKS + WO_BLKS + RT_BLKS) {
        int idx = (bx - WQ_BLKS - WO_BLKS) * 256 + tid;
        if (idx >= SEQ * 64) return;
        int n = idx >> 6, j = idx & 63;
        float pf = __bfloat162float(__float2bfloat16(
                       (float)pow(10000.0, (double)j * (1.0 / 64.0))));
        float th = __bfloat162float(__float2bfloat16(1.0f / pf));
        float sn, cs;
        sincosf((float)n * th, &sn, &cs);
        g_rope[idx] = make_float2(cs, sn);
    } else {
        int i = (bx - WQ_BLKS - WO_BLKS - RT_BLKS) * 256 + tid;
        if (i >= MTOT * EMB / 4) return;
        float4 v = ((const float4*)X)[i];
        float f[4] = {v.x, v.y, v.z, v.w};
        float h[4];
#pragma unroll
        for (int j = 0; j < 4; j++) h[j] = __half2float(__float2half_rn(f[j]));
        ((uint2*)Xhi)[i] = make_uint2(pack_f16x2(f[0], f[1]), pack_f16x2(f[2], f[3]));
        ((uint2*)Xlo)[i] = make_uint2(pack_f16x2(f[0] - h[0], f[1] - h[1]),
                                      pack_f16x2(f[2] - h[2], f[3] - h[3]));
    }
}

// ---------------------------------------------------------------------------
// Flash attention (unchanged)
// ---------------------------------------------------------------------------
#define FA_QBYTES   32768
#define FA_KVMAT    16384
#define FA_STAGE    (4 * FA_KVMAT)
#define FA_SMEM     (2 * FA_QBYTES + 2 * FA_STAGE)

__device__ __forceinline__ void fa_load_kv(uint32_t st,
    const __nv_bfloat16* kh, const __nv_bfloat16* kl,
    const __nv_bfloat16* vh, const __nv_bfloat16* vl, int tid)
{
#pragma unroll
    for (int i = 0; i < 4; i++) {
        int uid = tid + (i << 8);
        int r = uid >> 4, u = uid & 15;
        uint32_t so = r * 256 + ((u ^ (r & 7)) << 4);
        size_t go = (size_t)r * 128 + u * 8;
        cp16(st + so,                kh + go);
        cp16(st + FA_KVMAT + so,     kl + go);
        cp16(st + 2 * FA_KVMAT + so, vh + go);
        cp16(st + 3 * FA_KVMAT + so, vl + go);
    }
}

__global__ __launch_bounds__(256)
void flash_mma_kernel(const __nv_bfloat16* __restrict__ Qh, const __nv_bfloat16* __restrict__ Ql,
                      const __nv_bfloat16* __restrict__ Kh, const __nv_bfloat16* __restrict__ Kl,
                      const __nv_bfloat16* __restrict__ Vh, const __nv_bfloat16* __restrict__ Vl,
                      __nv_bfloat16* __restrict__ Ohi, __nv_bfloat16* __restrict__ Olo)
{
    extern __shared__ __align__(1024) char sm[];
    const uint32_t sb = smem_u32(sm);
    const int tid = threadIdx.x, lane = tid & 31, w = tid >> 5;
    const int qb = gridDim.x - 1 - blockIdx.x;
    const int bh = blockIdx.y;
    const int row_lo = qb * 128 + w * 16;
    const uint32_t sQh = sb, sQl = sb + FA_QBYTES;
    const uint32_t sKV = sb + 2 * FA_QBYTES;

    {
        const __nv_bfloat16* qhg = Qh + ((size_t)bh * SEQ + qb * 128) * DHEAD;
        const __nv_bfloat16* qlg = Ql + ((size_t)bh * SEQ + qb * 128) * DHEAD;
#pragma unroll
        for (int i = 0; i < 8; i++) {
            int uid = tid + (i << 8);
            int r = uid >> 4, u = uid & 15;
            uint32_t so = r * 256 + ((u ^ (r & 7)) << 4);
            size_t go = (size_t)r * 128 + u * 8;
            cp16(sQh + so, qhg + go);
            cp16(sQl + so, qlg + go);
        }
    }
    const __nv_bfloat16* khb = Kh + (size_t)bh * SEQ * DHEAD;
    const __nv_bfloat16* klb = Kl + (size_t)bh * SEQ * DHEAD;
    const __nv_bfloat16* vhb = Vh + (size_t)bh * SEQ * DHEAD;
    const __nv_bfloat16* vlb = Vl + (size_t)bh * SEQ * DHEAD;

    fa_load_kv(sKV, khb, klb, vhb, vlb, tid);
    CP_COMMIT();

    float O[16][4];
#pragma unroll
    for (int i = 0; i < 16; i++)
#pragma unroll
        for (int j = 0; j < 4; j++) O[i][j] = 0.f;
    float mrow0 = -1e30f, mrow1 = -1e30f, lrow0 = 0.f, lrow1 = 0.f;

    const float SC = 0.08838834764831845f * 1.4426950408889634f;
    const int nkb = 2 * qb + 2;

    for (int kb = 0; kb < nkb; kb++) {
        const uint32_t st = sKV + (kb & 1) * FA_STAGE;
        if (kb + 1 < nkb) {
            fa_load_kv(sKV + ((kb + 1) & 1) * FA_STAGE,
                       khb + (size_t)(kb + 1) * 64 * DHEAD, klb + (size_t)(kb + 1) * 64 * DHEAD,
                       vhb + (size_t)(kb + 1) * 64 * DHEAD, vlb + (size_t)(kb + 1) * 64 * DHEAD, tid);
            CP_COMMIT();
            CP_WAIT(1);
        } else {
            CP_WAIT(0);
        }
        __syncthreads();

        const bool skip = (kb * 64 > row_lo + 15);
        if (!skip) {
            float S[8][4];
#pragma unroll
            for (int i = 0; i < 8; i++)
#pragma unroll
                for (int j = 0; j < 4; j++) S[i][j] = 0.f;

            const int ar = w * 16 + (lane & 7) + ((lane >> 3) & 1) * 8;
            const int br_ = ((lane >> 4) << 3) + (lane & 7);
            const int au = (lane >> 4);
            const int bu = ((lane >> 3) & 1);
#pragma unroll
            for (int ks = 0; ks < 8; ks++) {
                uint32_t qa[4], ql4[4];
                uint32_t aoff = ar * 256 + (((2 * ks + au) ^ (ar & 7)) << 4);
                ldsm_x4(qa, sQh + aoff);
                ldsm_x4(ql4, sQl + aoff);
                uint32_t kh4[4][4], kl4[4][4];
#pragma unroll
                for (int ng = 0; ng < 4; ng++) {
                    int br = ng * 16 + br_;
                    uint32_t boff = br * 256 + (((2 * ks + bu) ^ (br & 7)) << 4);
                    ldsm_x4(kh4[ng], st + boff);
                    ldsm_x4(kl4[ng], st + FA_KVMAT + boff);
                }
#pragma unroll
                for (int ng = 0; ng < 4; ng++) {
                    mma_bf16(S[2 * ng],     qa, kh4[ng][0], kh4[ng][1]);
                    mma_bf16(S[2 * ng + 1], qa, kh4[ng][2], kh4[ng][3]);
                }
#pragma unroll
                for (int ng = 0; ng < 4; ng++) {
                    mma_bf16(S[2 * ng],     ql4, kh4[ng][0], kh4[ng][1]);
                    mma_bf16(S[2 * ng + 1], ql4, kh4[ng][2], kh4[ng][3]);
                }
#pragma unroll
                for (int ng = 0; ng < 4; ng++) {
                    mma_bf16(S[2 * ng],     qa, kl4[ng][0], kl4[ng][1]);
                    mma_bf16(S[2 * ng + 1], qa, kl4[ng][2], kl4[ng][3]);
                }
            }

            const int r0 = row_lo + (lane >> 2), r1 = r0 + 8;
            const int c00 = kb * 64 + (lane & 3) * 2;
            float m0p = -1e30f, m1p = -1e30f;
#pragma unroll
            for (int nt = 0; nt < 8; nt++) {
                int c = c00 + nt * 8;
#pragma unroll
                for (int j = 0; j < 4; j++) {
                    int col = c + (j & 1);
                    int row = (j < 2) ? r0 : r1;
                    float s = S[nt][j] * SC;
                    if (col > row) s = -1e30f;
                    S[nt][j] = s;
                }
                m0p = fmaxf(m0p, fmaxf(S[nt][0], S[nt][1]));
                m1p = fmaxf(m1p, fmaxf(S[nt][2], S[nt][3]));
            }
            m0p = fmaxf(m0p, __shfl_xor_sync(0xffffffffu, m0p, 1));
            m0p = fmaxf(m0p, __shfl_xor_sync(0xffffffffu, m0p, 2));
            m1p = fmaxf(m1p, __shfl_xor_sync(0xffffffffu, m1p, 1));
            m1p = fmaxf(m1p, __shfl_xor_sync(0xffffffffu, m1p, 2));
            const float mn0 = fmaxf(mrow0, m0p), mn1 = fmaxf(mrow1, m1p);
            const float a0 = ex2f(mrow0 - mn0), a1 = ex2f(mrow1 - mn1);
            mrow0 = mn0; mrow1 = mn1;
            float ps0 = 0.f, ps1 = 0.f;
#pragma unroll
            for (int nt = 0; nt < 8; nt++) {
                S[nt][0] = ex2f(S[nt][0] - mn0);
                S[nt][1] = ex2f(S[nt][1] - mn0);
                S[nt][2] = ex2f(S[nt][2] - mn1);
                S[nt][3] = ex2f(S[nt][3] - mn1);
                ps0 += S[nt][0] + S[nt][1];
                ps1 += S[nt][2] + S[nt][3];
            }
            lrow0 = lrow0 * a0 + ps0;
            lrow1 = lrow1 * a1 + ps1;
#pragma unroll
            for (int dt = 0; dt < 16; dt++) {
                O[dt][0] *= a0; O[dt][1] *= a0;
                O[dt][2] *= a1; O[dt][3] *= a1;
            }

            const int vr_ = (lane & 7) + ((lane >> 3) & 1) * 8;
            const int vu_ = (lane >> 4);
#pragma unroll
            for (int ks2 = 0; ks2 < 4; ks2++) {
                uint32_t ph[4], pl[4];
                {
                    float p0 = S[2 * ks2][0], p1 = S[2 * ks2][1];
                    float p2 = S[2 * ks2][2], p3 = S[2 * ks2][3];
                    float p4 = S[2 * ks2 + 1][0], p5 = S[2 * ks2 + 1][1];
                    float p6 = S[2 * ks2 + 1][2], p7 = S[2 * ks2 + 1][3];
                    ph[0] = pack_bf16x2(p0, p1);
                    ph[1] = pack_bf16x2(p2, p3);
                    ph[2] = pack_bf16x2(p4, p5);
                    ph[3] = pack_bf16x2(p6, p7);
#define RES(x) ((x) - __bfloat162float(__float2bfloat16(x)))
                    pl[0] = pack_bf16x2(RES(p0), RES(p1));
                    pl[1] = pack_bf16x2(RES(p2), RES(p3));
                    pl[2] = pack_bf16x2(RES(p4), RES(p5));
                    pl[3] = pack_bf16x2(RES(p6), RES(p7));
#undef RES
                }
                int vr = ks2 * 16 + vr_;
#pragma unroll
                for (int dp = 0; dp < 8; dp++) {
                    uint32_t voff = vr * 256 + (((dp * 2 + vu_) ^ (vr & 7)) << 4);
                    uint32_t vh4[4], vl4[4];
                    ldsm_x4_t(vh4, st + 2 * FA_KVMAT + voff);
                    ldsm_x4_t(vl4, st + 3 * FA_KVMAT + voff);
                    mma_bf16(O[2 * dp],     ph, vh4[0], vh4[1]);
                    mma_bf16(O[2 * dp + 1], ph, vh4[2], vh4[3]);
                    mma_bf16(O[2 * dp],     pl, vh4[0], vh4[1]);
                    mma_bf16(O[2 * dp + 1], pl, vh4[2], vh4[3]);
                    mma_bf16(O[2 * dp],     ph, vl4[0], vl4[1]);
                    mma_bf16(O[2 * dp + 1], ph, vl4[2], vl4[3]);
                }
            }
        }
        __syncthreads();
    }

    float l0 = lrow0;
    l0 += __shfl_xor_sync(0xffffffffu, l0, 1);
    l0 += __shfl_xor_sync(0xffffffffu, l0, 2);
    float l1 = lrow1;
    l1 += __shfl_xor_sync(0xffffffffu, l1, 1);
    l1 += __shfl_xor_sync(0xffffffffu, l1, 2);
    const float inv0 = 1.0f / l0, inv1 = 1.0f / l1;

    const int b = bh >> 4, h = bh & 15;
    const int n0r = row_lo + (lane >> 2);
    size_t base0 = ((size_t)(b * SEQ + n0r)) * EMB + h * DHEAD + (lane & 3) * 2;
    size_t base1 = base0 + (size_t)8 * EMB;
#pragma unroll
    for (int dt = 0; dt < 16; dt++) {
        float x0 = O[dt][0] * inv0, x1 = O[dt][1] * inv0;
        float x2 = O[dt][2] * inv1, x3 = O[dt][3] * inv1;
        float h0 = __bfloat162float(__float2bfloat16(x0));
        float h1 = __bfloat162float(__float2bfloat16(x1));
        float h2 = __bfloat162float(__float2bfloat16(x2));
        float h3 = __bfloat162float(__float2bfloat16(x3));
        *(uint32_t*)&Ohi[base0 + dt * 8] = pack_bf16x2(x0, x1);
        *(uint32_t*)&Olo[base0 + dt * 8] = pack_bf16x2(x0 - h0, x1 - h1);
        *(uint32_t*)&Ohi[base1 + dt * 8] = pack_bf16x2(x2, x3);
        *(uint32_t*)&Olo[base1 + dt * 8] = pack_bf16x2(x2 - h2, x3 - h3);
    }
}

// ---------------------------------------------------------------------------
// Launch
// ---------------------------------------------------------------------------
extern "C" void kernel_launch(void* const* d_in, const int* in_sizes, int n_in,
                              void* d_out, int out_size)
{
    const float* x    = (const float*)d_in[0];
    const float* Wqkv = (const float*)d_in[1];
    const float* bqkv = (const float*)d_in[2];
    const float* Wo   = (const float*)d_in[3];
    const float* bo   = (const float*)d_in[4];
    float* out = (float*)d_out;
    (void)in_sizes; (void)n_in; (void)out_size;

    __nv_bfloat16 *qhi, *qlo, *khi, *klo, *vhi, *vlo, *ahi, *alo, *wohi, *wolo;
    __half *xh16, *xl16, *wq16;
    cudaGetSymbolAddress((void**)&qhi,  g_qhi);
    cudaGetSymbolAddress((void**)&qlo,  g_qlo);
    cudaGetSymbolAddress((void**)&khi,  g_khi);
    cudaGetSymbolAddress((void**)&klo,  g_klo);
    cudaGetSymbolAddress((void**)&vhi,  g_vhi);
    cudaGetSymbolAddress((void**)&vlo,  g_vlo);
    cudaGetSymbolAddress((void**)&ahi,  g_ahi);
    cudaGetSymbolAddress((void**)&alo,  g_alo);
    cudaGetSymbolAddress((void**)&wohi, g_wohi);
    cudaGetSymbolAddress((void**)&wolo, g_wolo);
    cudaGetSymbolAddress((void**)&xh16, g_xh16);
    cudaGetSymbolAddress((void**)&xl16, g_xl16);
    cudaGetSymbolAddress((void**)&wq16, g_wq16);

    cudaFuncSetAttribute(gemm_qkv_rope_kernel,
                         cudaFuncAttributeMaxDynamicSharedMemorySize, GEMMF_SMEM);
    cudaFuncSetAttribute(gemm_mma_kernel,
                         cudaFuncAttributeMaxDynamicSharedMemorySize, GEMM_SMEM);
    cudaFuncSetAttribute(flash_mma_kernel,
                         cudaFuncAttributeMaxDynamicSharedMemorySize, FA_SMEM);

    // 1) merged prep (one launch)
    prep_all_kernel<<<PREP_BLKS, 256>>>(Wqkv, wq16, Wo, wohi, wolo, x, xh16, xl16);

    // 2) QKV projection + fused RoPE/split (BM=128, 4-stage, vectorized epi)
    gemm_qkv_rope_kernel<<<dim3(NQKV / 128, MTOT / 128), 256, GEMMF_SMEM>>>(
        xh16, xl16, wq16, bqkv, qhi, qlo, khi, klo, vhi, vlo);

    // 3) Flash attention -> out-proj A hi/lo directly
    flash_mma_kernel<<<dim3(SEQ / 128, BHT), 256, FA_SMEM>>>(
        qhi, qlo, khi, klo, vhi, vlo, ahi, alo);

    // 4) Output projection — bf16 3-pass
    gemm_mma_kernel<<<dim3(EMB / 128, MTOT / 128), 256, GEMM_SMEM>>>(
        ahi, alo, wohi, wolo, bo, out, EMB);
}